// round 1
// baseline (speedup 1.0000x reference)
#include <cuda_runtime.h>
#include <cstdint>
#include <math.h>

#define NB 4
#define NS 2048
#define NE 1024
#define NH 16
#define NHD 64

// Scratch (allocation-free rules: __device__ globals)
__device__ __align__(256) float g_qkv[(size_t)NB * NS * 3 * NE];   // [B*S, 3E]
__device__ __align__(256) float g_attn[(size_t)NB * NS * NE];      // [B*S, E] joined layout

__device__ __forceinline__ uint32_t f2tf(float x) {
    uint32_t r;
    asm("cvt.rna.tf32.f32 %0, %1;" : "=r"(r) : "f"(x));
    return r;
}

__device__ __forceinline__ void mma_tf32(float* c, const uint32_t* a, uint32_t b0, uint32_t b1) {
    asm volatile(
        "mma.sync.aligned.m16n8k8.row.col.f32.tf32.tf32.f32 "
        "{%0,%1,%2,%3},{%4,%5,%6,%7},{%8,%9},{%0,%1,%2,%3};\n"
        : "+f"(c[0]), "+f"(c[1]), "+f"(c[2]), "+f"(c[3])
        : "r"(a[0]), "r"(a[1]), "r"(a[2]), "r"(a[3]), "r"(b0), "r"(b1));
}

// ---------------------------------------------------------------------------
// C[M,N] = A[M,K] @ B[K,N] + bias   (row-major, tf32 mma, fp32 accumulate)
// Block tile 128x128, K-tile 16, 256 threads = 8 warps (2x4), warp tile 64x32.
// ---------------------------------------------------------------------------
__global__ __launch_bounds__(256, 2)
void gemm_bias_tf32(const float* __restrict__ A, const float* __restrict__ Bm,
                    const float* __restrict__ bias, float* __restrict__ C,
                    int M, int N, int K)
{
    __shared__ uint32_t As[16][132];   // [k][m], pad 4 -> conflict-free frag loads
    __shared__ uint32_t Bs[16][132];   // [k][n]

    const int tid  = threadIdx.x;
    const int w    = tid >> 5;
    const int lane = tid & 31;
    const int g    = lane >> 2;
    const int tig  = lane & 3;
    const int wm   = w >> 2;           // 0..1
    const int wn   = w & 3;            // 0..3
    const int bm   = blockIdx.y * 128;
    const int bn   = blockIdx.x * 128;

    // global-load mapping
    const int ar  = tid >> 2;          // A rows: ar, ar+64
    const int ac4 = tid & 3;           // A cols: ac4*4 .. +3
    const int br  = tid >> 5;          // B rows: br, br+8
    const int bc4 = tid & 31;          // B cols: bc4*4 .. +3

    float4 a0r, a1r, b0r, b1r;

    // prologue load k0 = 0
    {
        a0r = *(const float4*)(A + (size_t)(bm + ar) * K + ac4 * 4);
        a1r = *(const float4*)(A + (size_t)(bm + ar + 64) * K + ac4 * 4);
        b0r = *(const float4*)(Bm + (size_t)(br) * N + bn + bc4 * 4);
        b1r = *(const float4*)(Bm + (size_t)(br + 8) * N + bn + bc4 * 4);
        As[ac4 * 4 + 0][ar] = f2tf(a0r.x);
        As[ac4 * 4 + 1][ar] = f2tf(a0r.y);
        As[ac4 * 4 + 2][ar] = f2tf(a0r.z);
        As[ac4 * 4 + 3][ar] = f2tf(a0r.w);
        As[ac4 * 4 + 0][ar + 64] = f2tf(a1r.x);
        As[ac4 * 4 + 1][ar + 64] = f2tf(a1r.y);
        As[ac4 * 4 + 2][ar + 64] = f2tf(a1r.z);
        As[ac4 * 4 + 3][ar + 64] = f2tf(a1r.w);
        uint4 bb0 = { f2tf(b0r.x), f2tf(b0r.y), f2tf(b0r.z), f2tf(b0r.w) };
        uint4 bb1 = { f2tf(b1r.x), f2tf(b1r.y), f2tf(b1r.z), f2tf(b1r.w) };
        *(uint4*)&Bs[br][bc4 * 4] = bb0;
        *(uint4*)&Bs[br + 8][bc4 * 4] = bb1;
    }
    __syncthreads();

    float acc[4][4][4];
    #pragma unroll
    for (int mt = 0; mt < 4; mt++)
        #pragma unroll
        for (int nt = 0; nt < 4; nt++)
            #pragma unroll
            for (int i = 0; i < 4; i++) acc[mt][nt][i] = 0.f;

    for (int k0 = 0; k0 < K; k0 += 16) {
        const bool nxt = (k0 + 16) < K;
        if (nxt) {
            const int kn = k0 + 16;
            a0r = *(const float4*)(A + (size_t)(bm + ar) * K + kn + ac4 * 4);
            a1r = *(const float4*)(A + (size_t)(bm + ar + 64) * K + kn + ac4 * 4);
            b0r = *(const float4*)(Bm + (size_t)(kn + br) * N + bn + bc4 * 4);
            b1r = *(const float4*)(Bm + (size_t)(kn + br + 8) * N + bn + bc4 * 4);
        }
        #pragma unroll
        for (int ks = 0; ks < 16; ks += 8) {
            uint32_t af[4][4], bf[4][2];
            #pragma unroll
            for (int mt = 0; mt < 4; mt++) {
                const int mr = wm * 64 + mt * 16;
                af[mt][0] = As[ks + tig][mr + g];
                af[mt][1] = As[ks + tig][mr + g + 8];
                af[mt][2] = As[ks + tig + 4][mr + g];
                af[mt][3] = As[ks + tig + 4][mr + g + 8];
            }
            #pragma unroll
            for (int nt = 0; nt < 4; nt++) {
                const int nc = wn * 32 + nt * 8;
                bf[nt][0] = Bs[ks + tig][nc + g];
                bf[nt][1] = Bs[ks + tig + 4][nc + g];
            }
            #pragma unroll
            for (int mt = 0; mt < 4; mt++)
                #pragma unroll
                for (int nt = 0; nt < 4; nt++)
                    mma_tf32(acc[mt][nt], af[mt], bf[nt][0], bf[nt][1]);
        }
        __syncthreads();
        if (nxt) {
            As[ac4 * 4 + 0][ar] = f2tf(a0r.x);
            As[ac4 * 4 + 1][ar] = f2tf(a0r.y);
            As[ac4 * 4 + 2][ar] = f2tf(a0r.z);
            As[ac4 * 4 + 3][ar] = f2tf(a0r.w);
            As[ac4 * 4 + 0][ar + 64] = f2tf(a1r.x);
            As[ac4 * 4 + 1][ar + 64] = f2tf(a1r.y);
            As[ac4 * 4 + 2][ar + 64] = f2tf(a1r.z);
            As[ac4 * 4 + 3][ar + 64] = f2tf(a1r.w);
            uint4 bb0 = { f2tf(b0r.x), f2tf(b0r.y), f2tf(b0r.z), f2tf(b0r.w) };
            uint4 bb1 = { f2tf(b1r.x), f2tf(b1r.y), f2tf(b1r.z), f2tf(b1r.w) };
            *(uint4*)&Bs[br][bc4 * 4] = bb0;
            *(uint4*)&Bs[br + 8][bc4 * 4] = bb1;
            __syncthreads();
        }
    }

    // epilogue: bias + store
    #pragma unroll
    for (int mt = 0; mt < 4; mt++) {
        const int row = bm + wm * 64 + mt * 16 + g;
        #pragma unroll
        for (int nt = 0; nt < 4; nt++) {
            const int col = bn + wn * 32 + nt * 8 + 2 * tig;
            const float bv0 = bias[col], bv1 = bias[col + 1];
            float2 v0 = { acc[mt][nt][0] + bv0, acc[mt][nt][1] + bv1 };
            float2 v1 = { acc[mt][nt][2] + bv0, acc[mt][nt][3] + bv1 };
            *(float2*)(C + (size_t)row * N + col) = v0;
            *(float2*)(C + (size_t)(row + 8) * N + col) = v1;
        }
    }
}

// ---------------------------------------------------------------------------
// Causal flash attention, tf32 mma.  One block per (qtile=64, head, batch).
// 4 warps; warp w owns query rows [qt*64 + 16w, +16).  HD = 64.
// qkv layout: [B*S, 3E]; q at col h*64, k at E + h*64, v at 2E + h*64.
// Output: joined layout [B*S, E], col h*64 + d.
// ---------------------------------------------------------------------------
__global__ __launch_bounds__(128)
void attn_tf32(const float* __restrict__ qkv, float* __restrict__ outp)
{
    __shared__ uint32_t Ks[64][68];      // [kv][d] tf32 bits
    __shared__ uint32_t Vs[64][68];      // [kv][d]
    __shared__ uint32_t Ps[4][16][68];   // per-warp P slice [qrow][kv]

    const int tid  = threadIdx.x;
    const int w    = tid >> 5;
    const int lane = tid & 31;
    const int g    = lane >> 2;
    const int tig  = lane & 3;
    const int qt   = blockIdx.x;
    const int h    = blockIdx.y;
    const int b    = blockIdx.z;

    const size_t rs = 3 * NE;
    const float* base = qkv + (size_t)b * NS * rs;
    const float* qptr = base + h * NHD;
    const float* kptr = base + NE + h * NHD;
    const float* vptr = base + 2 * NE + h * NHD;

    const int qrow0 = qt * 64 + w * 16;

    // Q fragments (scaled by 1/sqrt(HD) = 0.125), kept in registers for all iters
    uint32_t qf[8][4];
    #pragma unroll
    for (int kt = 0; kt < 8; kt++) {
        const float* r0 = qptr + (size_t)(qrow0 + g) * rs + kt * 8;
        const float* r1 = qptr + (size_t)(qrow0 + g + 8) * rs + kt * 8;
        qf[kt][0] = f2tf(0.125f * __ldg(r0 + tig));
        qf[kt][1] = f2tf(0.125f * __ldg(r1 + tig));
        qf[kt][2] = f2tf(0.125f * __ldg(r0 + tig + 4));
        qf[kt][3] = f2tf(0.125f * __ldg(r1 + tig + 4));
    }

    float o[8][4];
    #pragma unroll
    for (int nt = 0; nt < 8; nt++)
        #pragma unroll
        for (int i = 0; i < 4; i++) o[nt][i] = 0.f;
    float m0 = -INFINITY, m1 = -INFINITY;
    float l0 = 0.f, l1 = 0.f;

    for (int j = 0; j <= qt; j++) {
        __syncthreads();   // guard K/V overwrite vs previous iter reads
        #pragma unroll
        for (int i = 0; i < 8; i++) {
            const int lin = tid + i * 128;       // 0..1023
            const int r   = lin >> 4;
            const int c4  = lin & 15;
            const float4 kv4 = *(const float4*)(kptr + (size_t)(j * 64 + r) * rs + c4 * 4);
            uint4 kk = { f2tf(kv4.x), f2tf(kv4.y), f2tf(kv4.z), f2tf(kv4.w) };
            *(uint4*)&Ks[r][c4 * 4] = kk;
            const float4 vv4 = *(const float4*)(vptr + (size_t)(j * 64 + r) * rs + c4 * 4);
            uint4 vv = { f2tf(vv4.x), f2tf(vv4.y), f2tf(vv4.z), f2tf(vv4.w) };
            *(uint4*)&Vs[r][c4 * 4] = vv;
        }
        __syncthreads();

        // scores S = Q @ K^T   (per warp: 16 x 64)
        float sc[8][4];
        #pragma unroll
        for (int nt = 0; nt < 8; nt++)
            #pragma unroll
            for (int i = 0; i < 4; i++) sc[nt][i] = 0.f;
        #pragma unroll
        for (int kt = 0; kt < 8; kt++) {
            #pragma unroll
            for (int nt = 0; nt < 8; nt++) {
                const uint32_t bb0 = Ks[nt * 8 + g][kt * 8 + tig];
                const uint32_t bb1 = Ks[nt * 8 + g][kt * 8 + tig + 4];
                mma_tf32(sc[nt], qf[kt], bb0, bb1);
            }
        }

        if (j == qt) {   // diagonal tile: elementwise causal mask
            const int r0g = qrow0 + g, r1g = qrow0 + g + 8;
            #pragma unroll
            for (int nt = 0; nt < 8; nt++) {
                const int col = j * 64 + nt * 8 + 2 * tig;
                if (col     > r0g) sc[nt][0] = -1e30f;
                if (col + 1 > r0g) sc[nt][1] = -1e30f;
                if (col     > r1g) sc[nt][2] = -1e30f;
                if (col + 1 > r1g) sc[nt][3] = -1e30f;
            }
        }

        // online softmax (per row-half; rows g and g+8 within warp slice)
        float mt0 = -1e30f, mt1 = -1e30f;
        #pragma unroll
        for (int nt = 0; nt < 8; nt++) {
            mt0 = fmaxf(mt0, fmaxf(sc[nt][0], sc[nt][1]));
            mt1 = fmaxf(mt1, fmaxf(sc[nt][2], sc[nt][3]));
        }
        mt0 = fmaxf(mt0, __shfl_xor_sync(0xffffffffu, mt0, 1));
        mt0 = fmaxf(mt0, __shfl_xor_sync(0xffffffffu, mt0, 2));
        mt1 = fmaxf(mt1, __shfl_xor_sync(0xffffffffu, mt1, 1));
        mt1 = fmaxf(mt1, __shfl_xor_sync(0xffffffffu, mt1, 2));

        const float mn0 = fmaxf(m0, mt0), mn1 = fmaxf(m1, mt1);
        const float al0 = __expf(m0 - mn0), al1 = __expf(m1 - mn1);
        m0 = mn0; m1 = mn1;

        float rs0 = 0.f, rs1 = 0.f;
        #pragma unroll
        for (int nt = 0; nt < 8; nt++) {
            const float p0 = __expf(sc[nt][0] - mn0);
            const float p1 = __expf(sc[nt][1] - mn0);
            const float p2 = __expf(sc[nt][2] - mn1);
            const float p3 = __expf(sc[nt][3] - mn1);
            rs0 += p0 + p1;
            rs1 += p2 + p3;
            Ps[w][g][nt * 8 + 2 * tig]         = f2tf(p0);
            Ps[w][g][nt * 8 + 2 * tig + 1]     = f2tf(p1);
            Ps[w][g + 8][nt * 8 + 2 * tig]     = f2tf(p2);
            Ps[w][g + 8][nt * 8 + 2 * tig + 1] = f2tf(p3);
            o[nt][0] *= al0; o[nt][1] *= al0;
            o[nt][2] *= al1; o[nt][3] *= al1;
        }
        rs0 += __shfl_xor_sync(0xffffffffu, rs0, 1);
        rs0 += __shfl_xor_sync(0xffffffffu, rs0, 2);
        rs1 += __shfl_xor_sync(0xffffffffu, rs1, 1);
        rs1 += __shfl_xor_sync(0xffffffffu, rs1, 2);
        l0 = l0 * al0 + rs0;
        l1 = l1 * al1 + rs1;

        __syncwarp();

        // O += P @ V
        #pragma unroll
        for (int kt = 0; kt < 8; kt++) {
            uint32_t af[4] = { Ps[w][g][kt * 8 + tig],     Ps[w][g + 8][kt * 8 + tig],
                               Ps[w][g][kt * 8 + tig + 4], Ps[w][g + 8][kt * 8 + tig + 4] };
            #pragma unroll
            for (int nt = 0; nt < 8; nt++) {
                mma_tf32(o[nt], af, Vs[kt * 8 + tig][nt * 8 + g],
                                    Vs[kt * 8 + tig + 4][nt * 8 + g]);
            }
        }
        __syncwarp();
    }

    const float inv0 = 1.f / l0, inv1 = 1.f / l1;
    const size_t orow0 = (size_t)b * NS + qrow0 + g;
    #pragma unroll
    for (int nt = 0; nt < 8; nt++) {
        const int col = h * NHD + nt * 8 + 2 * tig;
        float2 v0 = { o[nt][0] * inv0, o[nt][1] * inv0 };
        float2 v1 = { o[nt][2] * inv1, o[nt][3] * inv1 };
        *(float2*)(outp + orow0 * NE + col) = v0;
        *(float2*)(outp + (orow0 + 8) * NE + col) = v1;
    }
}

// ---------------------------------------------------------------------------
extern "C" void kernel_launch(void* const* d_in, const int* in_sizes, int n_in,
                              void* d_out, int out_size)
{
    (void)in_sizes; (void)n_in; (void)out_size;
    const float* Q  = (const float*)d_in[0];
    const float* Wp = (const float*)d_in[1];
    const float* bp = (const float*)d_in[2];
    const float* Wo = (const float*)d_in[3];
    const float* bo = (const float*)d_in[4];
    float* out = (float*)d_out;

    void* qkv_p = nullptr; void* attn_p = nullptr;
    cudaGetSymbolAddress(&qkv_p, g_qkv);
    cudaGetSymbolAddress(&attn_p, g_attn);
    float* qkv  = (float*)qkv_p;
    float* attn = (float*)attn_p;

    const int M = NB * NS;  // 8192
    gemm_bias_tf32<<<dim3((3 * NE) / 128, M / 128), 256>>>(Q, Wp, bp, qkv, M, 3 * NE, NE);
    attn_tf32<<<dim3(NS / 64, NH, NB), 128>>>(qkv, attn);
    gemm_bias_tf32<<<dim3(NE / 128, M / 128), 256>>>(attn, Wo, bo, out, M, NE, NE);
}

// round 4
// speedup vs baseline: 1.0832x; 1.0832x over previous
#include <cuda_runtime.h>
#include <cstdint>
#include <math.h>

#define NB 4
#define NS 2048
#define NE 1024
#define NH 16
#define NHD 64

// Scratch (allocation-free rules: __device__ globals)
__device__ __align__(256) float g_qkv[(size_t)NB * NS * 3 * NE];   // [B*S, 3E]
__device__ __align__(256) float g_attn[(size_t)NB * NS * NE];      // [B*S, E] joined layout

__device__ __forceinline__ uint32_t f2tf(float x) {
    uint32_t r;
    asm("cvt.rna.tf32.f32 %0, %1;" : "=r"(r) : "f"(x));
    return r;
}

__device__ __forceinline__ void mma_tf32(float* c, const uint32_t* a, uint32_t b0, uint32_t b1) {
    asm volatile(
        "mma.sync.aligned.m16n8k8.row.col.f32.tf32.tf32.f32 "
        "{%0,%1,%2,%3},{%4,%5,%6,%7},{%8,%9},{%0,%1,%2,%3};\n"
        : "+f"(c[0]), "+f"(c[1]), "+f"(c[2]), "+f"(c[3])
        : "r"(a[0]), "r"(a[1]), "r"(a[2]), "r"(a[3]), "r"(b0), "r"(b1));
}

// Swizzled index into a [16][136] tile: row stride 136 (=8 mod 32 banks),
// column XORed by ((row>>2)&3)<<3.  Conflict-free for both the transposed
// stores and the mma fragment loads (verified bank math by hand).
#define SWZ(r, c) ((r) * 136 + ((c) ^ ((((r) >> 2) & 3) << 3)))

// ---------------------------------------------------------------------------
// C[M,N] = A[M,K] @ B[K,N] + bias   (row-major, tf32 mma, fp32 accumulate)
// Block tile 128x128, K-tile 16, 256 threads = 8 warps (2x4), warp tile 64x32.
// Double-buffered smem, swizzled conflict-free layout.
// ---------------------------------------------------------------------------
__global__ __launch_bounds__(256, 2)
void gemm_bias_tf32(const float* __restrict__ A, const float* __restrict__ Bm,
                    const float* __restrict__ bias, float* __restrict__ C,
                    int M, int N, int K)
{
    __shared__ uint32_t As[2][16 * 136];   // [k][m] swizzled
    __shared__ uint32_t Bs[2][16 * 136];   // [k][n] swizzled

    const int tid  = threadIdx.x;
    const int w    = tid >> 5;
    const int lane = tid & 31;
    const int g    = lane >> 2;
    const int tig  = lane & 3;
    const int wm   = w >> 2;           // 0..1
    const int wn   = w & 3;            // 0..3
    const int bm   = blockIdx.y * 128;
    const int bn   = blockIdx.x * 128;

    // global-load mapping
    const int ar  = tid >> 2;          // A rows: ar, ar+64
    const int ac4 = tid & 3;           // A cols: ac4*4 .. +3
    const int br  = tid >> 5;          // B rows: br, br+8
    const int bc4 = lane;              // B cols: bc4*4 .. +3

    float4 a0r, a1r, b0r, b1r;

    // prologue: load + store k0 = 0 into buffer 0
    {
        a0r = *(const float4*)(A + (size_t)(bm + ar) * K + ac4 * 4);
        a1r = *(const float4*)(A + (size_t)(bm + ar + 64) * K + ac4 * 4);
        b0r = *(const float4*)(Bm + (size_t)(br) * N + bn + bc4 * 4);
        b1r = *(const float4*)(Bm + (size_t)(br + 8) * N + bn + bc4 * 4);
        As[0][SWZ(ac4 * 4 + 0, ar)] = f2tf(a0r.x);
        As[0][SWZ(ac4 * 4 + 1, ar)] = f2tf(a0r.y);
        As[0][SWZ(ac4 * 4 + 2, ar)] = f2tf(a0r.z);
        As[0][SWZ(ac4 * 4 + 3, ar)] = f2tf(a0r.w);
        As[0][SWZ(ac4 * 4 + 0, ar + 64)] = f2tf(a1r.x);
        As[0][SWZ(ac4 * 4 + 1, ar + 64)] = f2tf(a1r.y);
        As[0][SWZ(ac4 * 4 + 2, ar + 64)] = f2tf(a1r.z);
        As[0][SWZ(ac4 * 4 + 3, ar + 64)] = f2tf(a1r.w);
        uint4 bb0 = { f2tf(b0r.x), f2tf(b0r.y), f2tf(b0r.z), f2tf(b0r.w) };
        uint4 bb1 = { f2tf(b1r.x), f2tf(b1r.y), f2tf(b1r.z), f2tf(b1r.w) };
        *(uint4*)&Bs[0][SWZ(br, bc4 * 4)] = bb0;
        *(uint4*)&Bs[0][SWZ(br + 8, bc4 * 4)] = bb1;
    }
    __syncthreads();

    float acc[4][4][4];
    #pragma unroll
    for (int mt = 0; mt < 4; mt++)
        #pragma unroll
        for (int nt = 0; nt < 4; nt++)
            #pragma unroll
            for (int i = 0; i < 4; i++) acc[mt][nt][i] = 0.f;

    int buf = 0;
    for (int k0 = 0; k0 < K; k0 += 16) {
        const bool nxt = (k0 + 16) < K;
        if (nxt) {
            const int kn = k0 + 16;
            a0r = *(const float4*)(A + (size_t)(bm + ar) * K + kn + ac4 * 4);
            a1r = *(const float4*)(A + (size_t)(bm + ar + 64) * K + kn + ac4 * 4);
            b0r = *(const float4*)(Bm + (size_t)(kn + br) * N + bn + bc4 * 4);
            b1r = *(const float4*)(Bm + (size_t)(kn + br + 8) * N + bn + bc4 * 4);
        }
        #pragma unroll
        for (int ks = 0; ks < 16; ks += 8) {
            uint32_t af[4][4], bf[4][2];
            const int r0 = ks + tig;         // rows r0, r0+4 of this k-block
            const int x0 = ((r0 >> 2) & 3) << 3;
            const int x1 = (((r0 + 4) >> 2) & 3) << 3;
            #pragma unroll
            for (int mt = 0; mt < 4; mt++) {
                const int mr = wm * 64 + mt * 16;
                af[mt][0] = As[buf][r0 * 136 + ((mr + g) ^ x0)];
                af[mt][1] = As[buf][r0 * 136 + ((mr + g + 8) ^ x0)];
                af[mt][2] = As[buf][(r0 + 4) * 136 + ((mr + g) ^ x1)];
                af[mt][3] = As[buf][(r0 + 4) * 136 + ((mr + g + 8) ^ x1)];
            }
            #pragma unroll
            for (int nt = 0; nt < 4; nt++) {
                const int nc = wn * 32 + nt * 8;
                bf[nt][0] = Bs[buf][r0 * 136 + ((nc + g) ^ x0)];
                bf[nt][1] = Bs[buf][(r0 + 4) * 136 + ((nc + g) ^ x1)];
            }
            #pragma unroll
            for (int mt = 0; mt < 4; mt++)
                #pragma unroll
                for (int nt = 0; nt < 4; nt++)
                    mma_tf32(acc[mt][nt], af[mt], bf[nt][0], bf[nt][1]);
        }
        if (nxt) {
            const int nb = buf ^ 1;
            As[nb][SWZ(ac4 * 4 + 0, ar)] = f2tf(a0r.x);
            As[nb][SWZ(ac4 * 4 + 1, ar)] = f2tf(a0r.y);
            As[nb][SWZ(ac4 * 4 + 2, ar)] = f2tf(a0r.z);
            As[nb][SWZ(ac4 * 4 + 3, ar)] = f2tf(a0r.w);
            As[nb][SWZ(ac4 * 4 + 0, ar + 64)] = f2tf(a1r.x);
            As[nb][SWZ(ac4 * 4 + 1, ar + 64)] = f2tf(a1r.y);
            As[nb][SWZ(ac4 * 4 + 2, ar + 64)] = f2tf(a1r.z);
            As[nb][SWZ(ac4 * 4 + 3, ar + 64)] = f2tf(a1r.w);
            uint4 bb0 = { f2tf(b0r.x), f2tf(b0r.y), f2tf(b0r.z), f2tf(b0r.w) };
            uint4 bb1 = { f2tf(b1r.x), f2tf(b1r.y), f2tf(b1r.z), f2tf(b1r.w) };
            *(uint4*)&Bs[nb][SWZ(br, bc4 * 4)] = bb0;
            *(uint4*)&Bs[nb][SWZ(br + 8, bc4 * 4)] = bb1;
        }
        __syncthreads();
        buf ^= 1;
    }

    // epilogue: bias + store
    #pragma unroll
    for (int mt = 0; mt < 4; mt++) {
        const int row = bm + wm * 64 + mt * 16 + g;
        #pragma unroll
        for (int nt = 0; nt < 4; nt++) {
            const int col = bn + wn * 32 + nt * 8 + 2 * tig;
            const float bv0 = __ldg(bias + col), bv1 = __ldg(bias + col + 1);
            float2 v0 = { acc[mt][nt][0] + bv0, acc[mt][nt][1] + bv1 };
            float2 v1 = { acc[mt][nt][2] + bv0, acc[mt][nt][3] + bv1 };
            *(float2*)(C + (size_t)row * N + col) = v0;
            *(float2*)(C + (size_t)(row + 8) * N + col) = v1;
        }
    }
}

// ---------------------------------------------------------------------------
// Causal flash attention, tf32 mma.  One block per (qtile=64, head, batch).
// 4 warps; warp w owns query rows [qt*64 + 16w, +16).  HD = 64.
// Pad 72 (row stride = 8 mod 32 banks) -> conflict-free K, V, P accesses.
// ---------------------------------------------------------------------------
__global__ __launch_bounds__(128)
void attn_tf32(const float* __restrict__ qkv, float* __restrict__ outp)
{
    __shared__ uint32_t Ks[64][72];      // [kv][d] tf32 bits
    __shared__ uint32_t Vs[64][72];      // [kv][d]
    __shared__ uint32_t Ps[4][16][72];   // per-warp P slice [qrow][kv]

    const int tid  = threadIdx.x;
    const int w    = tid >> 5;
    const int lane = tid & 31;
    const int g    = lane >> 2;
    const int tig  = lane & 3;
    const int qt   = blockIdx.x;
    const int h    = blockIdx.y;
    const int b    = blockIdx.z;

    const size_t rs = 3 * NE;
    const float* base = qkv + (size_t)b * NS * rs;
    const float* qptr = base + h * NHD;
    const float* kptr = base + NE + h * NHD;
    const float* vptr = base + 2 * NE + h * NHD;

    const int qrow0 = qt * 64 + w * 16;

    // Q fragments (scaled by 1/sqrt(HD) = 0.125), kept in registers for all iters
    uint32_t qf[8][4];
    #pragma unroll
    for (int kt = 0; kt < 8; kt++) {
        const float* r0 = qptr + (size_t)(qrow0 + g) * rs + kt * 8;
        const float* r1 = qptr + (size_t)(qrow0 + g + 8) * rs + kt * 8;
        qf[kt][0] = f2tf(0.125f * __ldg(r0 + tig));
        qf[kt][1] = f2tf(0.125f * __ldg(r1 + tig));
        qf[kt][2] = f2tf(0.125f * __ldg(r0 + tig + 4));
        qf[kt][3] = f2tf(0.125f * __ldg(r1 + tig + 4));
    }

    float o[8][4];
    #pragma unroll
    for (int nt = 0; nt < 8; nt++)
        #pragma unroll
        for (int i = 0; i < 4; i++) o[nt][i] = 0.f;
    float m0 = -INFINITY, m1 = -INFINITY;
    float l0 = 0.f, l1 = 0.f;

    for (int j = 0; j <= qt; j++) {
        __syncthreads();   // guard K/V overwrite vs previous iter reads
        #pragma unroll
        for (int i = 0; i < 8; i++) {
            const int lin = tid + i * 128;       // 0..1023
            const int r   = lin >> 4;
            const int c4  = lin & 15;
            const float4 kv4 = *(const float4*)(kptr + (size_t)(j * 64 + r) * rs + c4 * 4);
            uint4 kk = { f2tf(kv4.x), f2tf(kv4.y), f2tf(kv4.z), f2tf(kv4.w) };
            *(uint4*)&Ks[r][c4 * 4] = kk;
            const float4 vv4 = *(const float4*)(vptr + (size_t)(j * 64 + r) * rs + c4 * 4);
            uint4 vv = { f2tf(vv4.x), f2tf(vv4.y), f2tf(vv4.z), f2tf(vv4.w) };
            *(uint4*)&Vs[r][c4 * 4] = vv;
        }
        __syncthreads();

        // scores S = Q @ K^T   (per warp: 16 x 64)
        float sc[8][4];
        #pragma unroll
        for (int nt = 0; nt < 8; nt++)
            #pragma unroll
            for (int i = 0; i < 4; i++) sc[nt][i] = 0.f;
        #pragma unroll
        for (int kt = 0; kt < 8; kt++) {
            #pragma unroll
            for (int nt = 0; nt < 8; nt++) {
                const uint32_t bb0 = Ks[nt * 8 + g][kt * 8 + tig];
                const uint32_t bb1 = Ks[nt * 8 + g][kt * 8 + tig + 4];
                mma_tf32(sc[nt], qf[kt], bb0, bb1);
            }
        }

        if (j == qt) {   // diagonal tile: elementwise causal mask
            const int r0g = qrow0 + g, r1g = qrow0 + g + 8;
            #pragma unroll
            for (int nt = 0; nt < 8; nt++) {
                const int col = j * 64 + nt * 8 + 2 * tig;
                if (col     > r0g) sc[nt][0] = -1e30f;
                if (col + 1 > r0g) sc[nt][1] = -1e30f;
                if (col     > r1g) sc[nt][2] = -1e30f;
                if (col + 1 > r1g) sc[nt][3] = -1e30f;
            }
        }

        // online softmax (per row-half; rows g and g+8 within warp slice)
        float mt0 = -1e30f, mt1 = -1e30f;
        #pragma unroll
        for (int nt = 0; nt < 8; nt++) {
            mt0 = fmaxf(mt0, fmaxf(sc[nt][0], sc[nt][1]));
            mt1 = fmaxf(mt1, fmaxf(sc[nt][2], sc[nt][3]));
        }
        mt0 = fmaxf(mt0, __shfl_xor_sync(0xffffffffu, mt0, 1));
        mt0 = fmaxf(mt0, __shfl_xor_sync(0xffffffffu, mt0, 2));
        mt1 = fmaxf(mt1, __shfl_xor_sync(0xffffffffu, mt1, 1));
        mt1 = fmaxf(mt1, __shfl_xor_sync(0xffffffffu, mt1, 2));

        const float mn0 = fmaxf(m0, mt0), mn1 = fmaxf(m1, mt1);
        const float al0 = __expf(m0 - mn0), al1 = __expf(m1 - mn1);
        m0 = mn0; m1 = mn1;

        float rs0 = 0.f, rs1 = 0.f;
        #pragma unroll
        for (int nt = 0; nt < 8; nt++) {
            const float p0 = __expf(sc[nt][0] - mn0);
            const float p1 = __expf(sc[nt][1] - mn0);
            const float p2 = __expf(sc[nt][2] - mn1);
            const float p3 = __expf(sc[nt][3] - mn1);
            rs0 += p0 + p1;
            rs1 += p2 + p3;
            uint2 pv0 = { f2tf(p0), f2tf(p1) };
            uint2 pv1 = { f2tf(p2), f2tf(p3) };
            *(uint2*)&Ps[w][g][nt * 8 + 2 * tig]     = pv0;
            *(uint2*)&Ps[w][g + 8][nt * 8 + 2 * tig] = pv1;
            o[nt][0] *= al0; o[nt][1] *= al0;
            o[nt][2] *= al1; o[nt][3] *= al1;
        }
        rs0 += __shfl_xor_sync(0xffffffffu, rs0, 1);
        rs0 += __shfl_xor_sync(0xffffffffu, rs0, 2);
        rs1 += __shfl_xor_sync(0xffffffffu, rs1, 1);
        rs1 += __shfl_xor_sync(0xffffffffu, rs1, 2);
        l0 = l0 * al0 + rs0;
        l1 = l1 * al1 + rs1;

        __syncwarp();

        // O += P @ V
        #pragma unroll
        for (int kt = 0; kt < 8; kt++) {
            uint32_t af[4] = { Ps[w][g][kt * 8 + tig],     Ps[w][g + 8][kt * 8 + tig],
                               Ps[w][g][kt * 8 + tig + 4], Ps[w][g + 8][kt * 8 + tig + 4] };
            #pragma unroll
            for (int nt = 0; nt < 8; nt++) {
                mma_tf32(o[nt], af, Vs[kt * 8 + tig][nt * 8 + g],
                                    Vs[kt * 8 + tig + 4][nt * 8 + g]);
            }
        }
        __syncwarp();
    }

    const float inv0 = 1.f / l0, inv1 = 1.f / l1;
    const size_t orow0 = (size_t)b * NS + qrow0 + g;
    #pragma unroll
    for (int nt = 0; nt < 8; nt++) {
        const int col = h * NHD + nt * 8 + 2 * tig;
        float2 v0 = { o[nt][0] * inv0, o[nt][1] * inv0 };
        float2 v1 = { o[nt][2] * inv1, o[nt][3] * inv1 };
        *(float2*)(outp + orow0 * NE + col) = v0;
        *(float2*)(outp + (orow0 + 8) * NE + col) = v1;
    }
}

// ---------------------------------------------------------------------------
extern "C" void kernel_launch(void* const* d_in, const int* in_sizes, int n_in,
                              void* d_out, int out_size)
{
    (void)in_sizes; (void)n_in; (void)out_size;
    const float* Q  = (const float*)d_in[0];
    const float* Wp = (const float*)d_in[1];
    const float* bp = (const float*)d_in[2];
    const float* Wo = (const float*)d_in[3];
    const float* bo = (const float*)d_in[4];
    float* out = (float*)d_out;

    void* qkv_p = nullptr; void* attn_p = nullptr;
    cudaGetSymbolAddress(&qkv_p, g_qkv);
    cudaGetSymbolAddress(&attn_p, g_attn);
    float* qkv  = (float*)qkv_p;
    float* attn = (float*)attn_p;

    const int M = NB * NS;  // 8192
    gemm_bias_tf32<<<dim3((3 * NE) / 128, M / 128), 256>>>(Q, Wp, bp, qkv, M, 3 * NE, NE);
    attn_tf32<<<dim3(NS / 64, NH, NB), 128>>>(qkv, attn);
    gemm_bias_tf32<<<dim3(NE / 128, M / 128), 256>>>(attn, Wo, bo, out, M, NE, NE);
}

// round 9
// speedup vs baseline: 1.1371x; 1.0498x over previous
#include <cuda_runtime.h>
#include <cstdint>
#include <math.h>

#define NB 4
#define NS 2048
#define NE 1024
#define NH 16
#define NHD 64

// Scratch (allocation-free rules: __device__ globals)
__device__ __align__(256) float g_qkv[(size_t)NB * NS * 3 * NE];   // [B*S, 3E]
__device__ __align__(256) float g_attn[(size_t)NB * NS * NE];      // [B*S, E] joined layout

__device__ __forceinline__ uint32_t f2tf(float x) {
    uint32_t r;
    asm("cvt.rna.tf32.f32 %0, %1;" : "=r"(r) : "f"(x));
    return r;
}

__device__ __forceinline__ void mma_tf32(float* c, const uint32_t* a, uint32_t b0, uint32_t b1) {
    asm volatile(
        "mma.sync.aligned.m16n8k8.row.col.f32.tf32.tf32.f32 "
        "{%0,%1,%2,%3},{%4,%5,%6,%7},{%8,%9},{%0,%1,%2,%3};\n"
        : "+f"(c[0]), "+f"(c[1]), "+f"(c[2]), "+f"(c[3])
        : "r"(a[0]), "r"(a[1]), "r"(a[2]), "r"(a[3]), "r"(b0), "r"(b1));
}

// ---------------------------------------------------------------------------
// C[M,N] = A[M,K] @ B[K,N] + bias   (row-major, tf32 mma, fp32 accumulate)
// Block tile 128x128, K-tile 16, 256 threads = 8 warps (2x4), warp tile 64x32.
// Double-buffered smem; swizzled layout with COMPILE-TIME-FOLDED offsets:
// addresses identical to the SWZ(r,c) = r*136 + (c ^ ((r>>2&3)<<3)) scheme,
// but decomposed so every fragment LDS is [base_reg + literal].
// ---------------------------------------------------------------------------
__global__ __launch_bounds__(256, 2)
void gemm_bias_tf32(const float* __restrict__ A, const float* __restrict__ Bm,
                    const float* __restrict__ bias, float* __restrict__ C,
                    int M, int N, int K)
{
    __shared__ uint32_t As[2][16 * 136];   // [k][m] swizzled
    __shared__ uint32_t Bs[2][16 * 136];   // [k][n] swizzled

    const int tid  = threadIdx.x;
    const int w    = tid >> 5;
    const int lane = tid & 31;
    const int g    = lane >> 2;
    const int tig  = lane & 3;
    const int wm   = w >> 2;           // 0..1
    const int wn   = w & 3;            // 0..3
    const int bm   = blockIdx.y * 128;
    const int bn   = blockIdx.x * 128;

    // global-load mapping
    const int ar  = tid >> 2;          // A rows: ar, ar+64
    const int ac4 = tid & 3;           // A cols: ac4*4 .. +3
    const int br  = tid >> 5;          // B rows: br, br+8
    const int bc4 = lane;              // B cols: bc4*4 .. +3

    // Hoisted swizzled store indices (loop-invariant):
    //   A store: SWZ(ac4*4+c, ar[+64]) = aSt + c*136 [+64]
    const int aSt  = ac4 * 544 + (ar ^ (ac4 << 3));
    //   B store: SWZ(br, bc4*4) and SWZ(br+8, bc4*4)
    const int bSt0 = br * 136 + ((bc4 * 4) ^ (((br >> 2) & 3) << 3));
    const int bSt1 = (br + 8) * 136 + ((bc4 * 4) ^ ((((br + 8) >> 2) & 3) << 3));

    // Hoisted fragment-load bases
    const int aBase = wm * 64 + g;     // bits 0-2 and 6 only (no bit 3/4/5 overlap w/ XOR)
    const int nBase = wn * 32 + g;

    float4 a0r, a1r, b0r, b1r;

    // prologue: load + store k0 = 0 into buffer 0
    {
        a0r = *(const float4*)(A + (size_t)(bm + ar) * K + ac4 * 4);
        a1r = *(const float4*)(A + (size_t)(bm + ar + 64) * K + ac4 * 4);
        b0r = *(const float4*)(Bm + (size_t)(br) * N + bn + bc4 * 4);
        b1r = *(const float4*)(Bm + (size_t)(br + 8) * N + bn + bc4 * 4);
        As[0][aSt + 0 * 136]      = f2tf(a0r.x);
        As[0][aSt + 1 * 136]      = f2tf(a0r.y);
        As[0][aSt + 2 * 136]      = f2tf(a0r.z);
        As[0][aSt + 3 * 136]      = f2tf(a0r.w);
        As[0][aSt + 0 * 136 + 64] = f2tf(a1r.x);
        As[0][aSt + 1 * 136 + 64] = f2tf(a1r.y);
        As[0][aSt + 2 * 136 + 64] = f2tf(a1r.z);
        As[0][aSt + 3 * 136 + 64] = f2tf(a1r.w);
        uint4 bb0 = { f2tf(b0r.x), f2tf(b0r.y), f2tf(b0r.z), f2tf(b0r.w) };
        uint4 bb1 = { f2tf(b1r.x), f2tf(b1r.y), f2tf(b1r.z), f2tf(b1r.w) };
        *(uint4*)&Bs[0][bSt0] = bb0;
        *(uint4*)&Bs[0][bSt1] = bb1;
    }
    __syncthreads();

    float acc[4][4][4];
    #pragma unroll
    for (int mt = 0; mt < 4; mt++)
        #pragma unroll
        for (int nt = 0; nt < 4; nt++)
            #pragma unroll
            for (int i = 0; i < 4; i++) acc[mt][nt][i] = 0.f;

    int buf = 0;
    for (int k0 = 0; k0 < K; k0 += 16) {
        const bool nxt = (k0 + 16) < K;
        if (nxt) {
            const int kn = k0 + 16;
            a0r = *(const float4*)(A + (size_t)(bm + ar) * K + kn + ac4 * 4);
            a1r = *(const float4*)(A + (size_t)(bm + ar + 64) * K + kn + ac4 * 4);
            b0r = *(const float4*)(Bm + (size_t)(kn + br) * N + bn + bc4 * 4);
            b1r = *(const float4*)(Bm + (size_t)(kn + br + 8) * N + bn + bc4 * 4);
        }
        #pragma unroll
        for (int ks = 0; ks < 16; ks += 8) {
            // For tig<4: x0 = ((ks+tig)>>2&3)<<3 is a LITERAL per unrolled ks.
            const int x0 = (ks == 0) ? 0 : 16;
            const int x1 = x0 + 8;
            const uint32_t* A0 = &As[buf][(ks + tig) * 136]     + aBase;
            const uint32_t* A1 = &As[buf][(ks + 4 + tig) * 136] + aBase;
            const uint32_t* B0 = &Bs[buf][(ks + tig) * 136]     + nBase;
            const uint32_t* B1 = &Bs[buf][(ks + 4 + tig) * 136] + nBase;
            uint32_t af[4][4], bf[4][2];
            #pragma unroll
            for (int mt = 0; mt < 4; mt++) {
                const int e0 = (mt * 16) ^ (x0 & 16);   // literal
                const int e1 = (mt * 16) ^ (x1 & 16);   // literal
                af[mt][0] = A0[e0 + (x0 & 8)];
                af[mt][1] = A0[e0 + (8 ^ (x0 & 8))];
                af[mt][2] = A1[e1 + (x1 & 8)];
                af[mt][3] = A1[e1 + (8 ^ (x1 & 8))];
            }
            #pragma unroll
            for (int nt = 0; nt < 4; nt++) {
                bf[nt][0] = B0[(nt * 8) ^ x0];          // literal offsets
                bf[nt][1] = B1[(nt * 8) ^ x1];
            }
            #pragma unroll
            for (int mt = 0; mt < 4; mt++)
                #pragma unroll
                for (int nt = 0; nt < 4; nt++)
                    mma_tf32(acc[mt][nt], af[mt], bf[nt][0], bf[nt][1]);
        }
        if (nxt) {
            const int nb = buf ^ 1;
            As[nb][aSt + 0 * 136]      = f2tf(a0r.x);
            As[nb][aSt + 1 * 136]      = f2tf(a0r.y);
            As[nb][aSt + 2 * 136]      = f2tf(a0r.z);
            As[nb][aSt + 3 * 136]      = f2tf(a0r.w);
            As[nb][aSt + 0 * 136 + 64] = f2tf(a1r.x);
            As[nb][aSt + 1 * 136 + 64] = f2tf(a1r.y);
            As[nb][aSt + 2 * 136 + 64] = f2tf(a1r.z);
            As[nb][aSt + 3 * 136 + 64] = f2tf(a1r.w);
            uint4 bb0 = { f2tf(b0r.x), f2tf(b0r.y), f2tf(b0r.z), f2tf(b0r.w) };
            uint4 bb1 = { f2tf(b1r.x), f2tf(b1r.y), f2tf(b1r.z), f2tf(b1r.w) };
            *(uint4*)&Bs[nb][bSt0] = bb0;
            *(uint4*)&Bs[nb][bSt1] = bb1;
        }
        __syncthreads();
        buf ^= 1;
    }

    // epilogue: bias + store
    #pragma unroll
    for (int mt = 0; mt < 4; mt++) {
        const int row = bm + wm * 64 + mt * 16 + g;
        #pragma unroll
        for (int nt = 0; nt < 4; nt++) {
            const int col = bn + wn * 32 + nt * 8 + 2 * tig;
            const float bv0 = __ldg(bias + col), bv1 = __ldg(bias + col + 1);
            float2 v0 = { acc[mt][nt][0] + bv0, acc[mt][nt][1] + bv1 };
            float2 v1 = { acc[mt][nt][2] + bv0, acc[mt][nt][3] + bv1 };
            *(float2*)(C + (size_t)row * N + col) = v0;
            *(float2*)(C + (size_t)(row + 8) * N + col) = v1;
        }
    }
}

// ---------------------------------------------------------------------------
// Causal flash attention, tf32 mma.  One block per (qtile=64, head, batch).
// 4 warps; warp w owns query rows [qt*64 + 16w, +16).  HD = 64.
// Pad 72 (row stride = 8 mod 32 banks) -> conflict-free K, V, P accesses.
// ---------------------------------------------------------------------------
__global__ __launch_bounds__(128)
void attn_tf32(const float* __restrict__ qkv, float* __restrict__ outp)
{
    __shared__ uint32_t Ks[64][72];      // [kv][d] tf32 bits
    __shared__ uint32_t Vs[64][72];      // [kv][d]
    __shared__ uint32_t Ps[4][16][72];   // per-warp P slice [qrow][kv]

    const int tid  = threadIdx.x;
    const int w    = tid >> 5;
    const int lane = tid & 31;
    const int g    = lane >> 2;
    const int tig  = lane & 3;
    const int qt   = blockIdx.x;
    const int h    = blockIdx.y;
    const int b    = blockIdx.z;

    const size_t rs = 3 * NE;
    const float* base = qkv + (size_t)b * NS * rs;
    const float* qptr = base + h * NHD;
    const float* kptr = base + NE + h * NHD;
    const float* vptr = base + 2 * NE + h * NHD;

    const int qrow0 = qt * 64 + w * 16;

    // Q fragments (scaled by 1/sqrt(HD) = 0.125), kept in registers for all iters
    uint32_t qf[8][4];
    #pragma unroll
    for (int kt = 0; kt < 8; kt++) {
        const float* r0 = qptr + (size_t)(qrow0 + g) * rs + kt * 8;
        const float* r1 = qptr + (size_t)(qrow0 + g + 8) * rs + kt * 8;
        qf[kt][0] = f2tf(0.125f * __ldg(r0 + tig));
        qf[kt][1] = f2tf(0.125f * __ldg(r1 + tig));
        qf[kt][2] = f2tf(0.125f * __ldg(r0 + tig + 4));
        qf[kt][3] = f2tf(0.125f * __ldg(r1 + tig + 4));
    }

    float o[8][4];
    #pragma unroll
    for (int nt = 0; nt < 8; nt++)
        #pragma unroll
        for (int i = 0; i < 4; i++) o[nt][i] = 0.f;
    float m0 = -INFINITY, m1 = -INFINITY;
    float l0 = 0.f, l1 = 0.f;

    for (int j = 0; j <= qt; j++) {
        __syncthreads();   // guard K/V overwrite vs previous iter reads
        #pragma unroll
        for (int i = 0; i < 8; i++) {
            const int lin = tid + i * 128;       // 0..1023
            const int r   = lin >> 4;
            const int c4  = lin & 15;
            const float4 kv4 = *(const float4*)(kptr + (size_t)(j * 64 + r) * rs + c4 * 4);
            uint4 kk = { f2tf(kv4.x), f2tf(kv4.y), f2tf(kv4.z), f2tf(kv4.w) };
            *(uint4*)&Ks[r][c4 * 4] = kk;
            const float4 vv4 = *(const float4*)(vptr + (size_t)(j * 64 + r) * rs + c4 * 4);
            uint4 vv = { f2tf(vv4.x), f2tf(vv4.y), f2tf(vv4.z), f2tf(vv4.w) };
            *(uint4*)&Vs[r][c4 * 4] = vv;
        }
        __syncthreads();

        // scores S = Q @ K^T   (per warp: 16 x 64)
        float sc[8][4];
        #pragma unroll
        for (int nt = 0; nt < 8; nt++)
            #pragma unroll
            for (int i = 0; i < 4; i++) sc[nt][i] = 0.f;
        #pragma unroll
        for (int kt = 0; kt < 8; kt++) {
            #pragma unroll
            for (int nt = 0; nt < 8; nt++) {
                const uint32_t bb0 = Ks[nt * 8 + g][kt * 8 + tig];
                const uint32_t bb1 = Ks[nt * 8 + g][kt * 8 + tig + 4];
                mma_tf32(sc[nt], qf[kt], bb0, bb1);
            }
        }

        if (j == qt) {   // diagonal tile: elementwise causal mask
            const int r0g = qrow0 + g, r1g = qrow0 + g + 8;
            #pragma unroll
            for (int nt = 0; nt < 8; nt++) {
                const int col = j * 64 + nt * 8 + 2 * tig;
                if (col     > r0g) sc[nt][0] = -1e30f;
                if (col + 1 > r0g) sc[nt][1] = -1e30f;
                if (col     > r1g) sc[nt][2] = -1e30f;
                if (col + 1 > r1g) sc[nt][3] = -1e30f;
            }
        }

        // online softmax (per row-half; rows g and g+8 within warp slice)
        float mt0 = -1e30f, mt1 = -1e30f;
        #pragma unroll
        for (int nt = 0; nt < 8; nt++) {
            mt0 = fmaxf(mt0, fmaxf(sc[nt][0], sc[nt][1]));
            mt1 = fmaxf(mt1, fmaxf(sc[nt][2], sc[nt][3]));
        }
        mt0 = fmaxf(mt0, __shfl_xor_sync(0xffffffffu, mt0, 1));
        mt0 = fmaxf(mt0, __shfl_xor_sync(0xffffffffu, mt0, 2));
        mt1 = fmaxf(mt1, __shfl_xor_sync(0xffffffffu, mt1, 1));
        mt1 = fmaxf(mt1, __shfl_xor_sync(0xffffffffu, mt1, 2));

        const float mn0 = fmaxf(m0, mt0), mn1 = fmaxf(m1, mt1);
        const float al0 = __expf(m0 - mn0), al1 = __expf(m1 - mn1);
        m0 = mn0; m1 = mn1;

        float rs0 = 0.f, rs1 = 0.f;
        #pragma unroll
        for (int nt = 0; nt < 8; nt++) {
            const float p0 = __expf(sc[nt][0] - mn0);
            const float p1 = __expf(sc[nt][1] - mn0);
            const float p2 = __expf(sc[nt][2] - mn1);
            const float p3 = __expf(sc[nt][3] - mn1);
            rs0 += p0 + p1;
            rs1 += p2 + p3;
            uint2 pv0 = { f2tf(p0), f2tf(p1) };
            uint2 pv1 = { f2tf(p2), f2tf(p3) };
            *(uint2*)&Ps[w][g][nt * 8 + 2 * tig]     = pv0;
            *(uint2*)&Ps[w][g + 8][nt * 8 + 2 * tig] = pv1;
            o[nt][0] *= al0; o[nt][1] *= al0;
            o[nt][2] *= al1; o[nt][3] *= al1;
        }
        rs0 += __shfl_xor_sync(0xffffffffu, rs0, 1);
        rs0 += __shfl_xor_sync(0xffffffffu, rs0, 2);
        rs1 += __shfl_xor_sync(0xffffffffu, rs1, 1);
        rs1 += __shfl_xor_sync(0xffffffffu, rs1, 2);
        l0 = l0 * al0 + rs0;
        l1 = l1 * al1 + rs1;

        __syncwarp();

        // O += P @ V
        #pragma unroll
        for (int kt = 0; kt < 8; kt++) {
            uint32_t af[4] = { Ps[w][g][kt * 8 + tig],     Ps[w][g + 8][kt * 8 + tig],
                               Ps[w][g][kt * 8 + tig + 4], Ps[w][g + 8][kt * 8 + tig + 4] };
            #pragma unroll
            for (int nt = 0; nt < 8; nt++) {
                mma_tf32(o[nt], af, Vs[kt * 8 + tig][nt * 8 + g],
                                    Vs[kt * 8 + tig + 4][nt * 8 + g]);
            }
        }
        __syncwarp();
    }

    const float inv0 = 1.f / l0, inv1 = 1.f / l1;
    const size_t orow0 = (size_t)b * NS + qrow0 + g;
    #pragma unroll
    for (int nt = 0; nt < 8; nt++) {
        const int col = h * NHD + nt * 8 + 2 * tig;
        float2 v0 = { o[nt][0] * inv0, o[nt][1] * inv0 };
        float2 v1 = { o[nt][2] * inv1, o[nt][3] * inv1 };
        *(float2*)(outp + orow0 * NE + col) = v0;
        *(float2*)(outp + (orow0 + 8) * NE + col) = v1;
    }
}

// ---------------------------------------------------------------------------
extern "C" void kernel_launch(void* const* d_in, const int* in_sizes, int n_in,
                              void* d_out, int out_size)
{
    (void)in_sizes; (void)n_in; (void)out_size;
    const float* Q  = (const float*)d_in[0];
    const float* Wp = (const float*)d_in[1];
    const float* bp = (const float*)d_in[2];
    const float* Wo = (const float*)d_in[3];
    const float* bo = (const float*)d_in[4];
    float* out = (float*)d_out;

    void* qkv_p = nullptr; void* attn_p = nullptr;
    cudaGetSymbolAddress(&qkv_p, g_qkv);
    cudaGetSymbolAddress(&attn_p, g_attn);
    float* qkv  = (float*)qkv_p;
    float* attn = (float*)attn_p;

    const int M = NB * NS;  // 8192
    gemm_bias_tf32<<<dim3((3 * NE) / 128, M / 128), 256>>>(Q, Wp, bp, qkv, M, 3 * NE, NE);
    attn_tf32<<<dim3(NS / 64, NH, NB), 128>>>(qkv, attn);
    gemm_bias_tf32<<<dim3(NE / 128, M / 128), 256>>>(attn, Wo, bo, out, M, NE, NE);
}

// round 10
// speedup vs baseline: 1.1743x; 1.0327x over previous
#include <cuda_runtime.h>
#include <cstdint>
#include <math.h>

#define NB 4
#define NS 2048
#define NE 1024
#define NH 16
#define NHD 64

// Scratch (allocation-free rules: __device__ globals)
__device__ __align__(256) float g_qkv[(size_t)NB * NS * 3 * NE];   // [B*S, 3E]
__device__ __align__(256) float g_attn[(size_t)NB * NS * NE];      // [B*S, E] joined layout

__device__ __forceinline__ uint32_t f2tf(float x) {
    uint32_t r;
    asm("cvt.rna.tf32.f32 %0, %1;" : "=r"(r) : "f"(x));
    return r;
}

__device__ __forceinline__ void mma_tf32(float* c, const uint32_t* a, uint32_t b0, uint32_t b1) {
    asm volatile(
        "mma.sync.aligned.m16n8k8.row.col.f32.tf32.tf32.f32 "
        "{%0,%1,%2,%3},{%4,%5,%6,%7},{%8,%9},{%0,%1,%2,%3};\n"
        : "+f"(c[0]), "+f"(c[1]), "+f"(c[2]), "+f"(c[3])
        : "r"(a[0]), "r"(a[1]), "r"(a[2]), "r"(a[3]), "r"(b0), "r"(b1));
}

__device__ __forceinline__ void ldsm_x4(uint32_t* r, uint32_t addr) {
    asm volatile("ldmatrix.sync.aligned.m8n8.x4.shared.b16 {%0,%1,%2,%3}, [%4];"
        : "=r"(r[0]), "=r"(r[1]), "=r"(r[2]), "=r"(r[3]) : "r"(addr));
}

__device__ __forceinline__ uint32_t smem_u32(const void* p) {
    return (uint32_t)__cvta_generic_to_shared(p);
}

// A-tile smem layout (words), m = row 0..127, c = 16B k-chunk 0..3.
// 2-row atoms of 32 words; slot permutation XOR (m>>1)&7 makes BOTH the
// STS.128 phases and the LDSM 8-row accesses tile all 32 banks (hand-checked).
__device__ __forceinline__ int a_off(int m, int c) {
    return ((m >> 1) * 32) + 4 * ((((m & 1) << 2) + c) ^ ((m >> 1) & 7));
}

// ---------------------------------------------------------------------------
// C[M,N] = A[M,K] @ B[K,N] + bias   (row-major, tf32 mma, fp32 accumulate)
// Block tile 128x128, K-tile 16, 256 threads = 8 warps (2x4), warp tile 64x32.
// Double-buffered smem.  A fragments via ldmatrix.x4 (loop-invariant addrs);
// B fragments via literal-offset scalar LDS (swizzled stride-136 layout).
// ---------------------------------------------------------------------------
__global__ __launch_bounds__(256, 2)
void gemm_bias_tf32(const float* __restrict__ A, const float* __restrict__ Bm,
                    const float* __restrict__ bias, float* __restrict__ C,
                    int M, int N, int K)
{
    __shared__ uint32_t As[2][2048];       // [m][k-chunk] permuted atoms (8KB/buf)
    __shared__ uint32_t Bs[2][16 * 136];   // [k][n] swizzled

    const int tid  = threadIdx.x;
    const int w    = tid >> 5;
    const int lane = tid & 31;
    const int g    = lane >> 2;
    const int tig  = lane & 3;
    const int wm   = w >> 2;           // 0..1
    const int wn   = w & 3;            // 0..3
    const int bm   = blockIdx.y * 128;
    const int bn   = blockIdx.x * 128;

    // global-load mapping
    const int ar  = tid >> 2;          // A rows: ar, ar+64
    const int ac4 = tid & 3;           // A cols: ac4*4 .. +3
    const int br  = tid >> 5;          // B rows: br, br+8
    const int bc4 = lane;              // B cols: bc4*4 .. +3

    // A store word indices (loop-invariant, STS.128 conflict-free)
    const int aSt0 = a_off(ar, ac4);
    const int aSt1 = a_off(ar + 64, ac4);

    // B store indices (swizzled, loop-invariant)
    const int bSt0 = br * 136 + ((bc4 * 4) ^ (((br >> 2) & 3) << 3));
    const int bSt1 = (br + 8) * 136 + ((bc4 * 4) ^ ((((br + 8) >> 2) & 3) << 3));

    // ldmatrix source addresses (loop-invariant per thread):
    // lane -> (matrix, row): lm = row within 16-row mt tile, lc = k-chunk half.
    const int lm = (((lane >> 3) & 1) << 3) + (lane & 7);
    const int lc = lane >> 4;
    const int mA = wm * 64 + lm;
    const uint32_t aLd0 = smem_u32(&As[0][a_off(mA, 0 + lc)]);  // ks = 0
    const uint32_t aLd8 = smem_u32(&As[0][a_off(mA, 2 + lc)]);  // ks = 8

    // B fragment base
    const int nBase = wn * 32 + g;

    float4 a0r, a1r, b0r, b1r;

    // prologue: load + store k0 = 0 into buffer 0
    {
        a0r = *(const float4*)(A + (size_t)(bm + ar) * K + ac4 * 4);
        a1r = *(const float4*)(A + (size_t)(bm + ar + 64) * K + ac4 * 4);
        b0r = *(const float4*)(Bm + (size_t)(br) * N + bn + bc4 * 4);
        b1r = *(const float4*)(Bm + (size_t)(br + 8) * N + bn + bc4 * 4);
        uint4 aa0 = { f2tf(a0r.x), f2tf(a0r.y), f2tf(a0r.z), f2tf(a0r.w) };
        uint4 aa1 = { f2tf(a1r.x), f2tf(a1r.y), f2tf(a1r.z), f2tf(a1r.w) };
        *(uint4*)&As[0][aSt0] = aa0;
        *(uint4*)&As[0][aSt1] = aa1;
        uint4 bb0 = { f2tf(b0r.x), f2tf(b0r.y), f2tf(b0r.z), f2tf(b0r.w) };
        uint4 bb1 = { f2tf(b1r.x), f2tf(b1r.y), f2tf(b1r.z), f2tf(b1r.w) };
        *(uint4*)&Bs[0][bSt0] = bb0;
        *(uint4*)&Bs[0][bSt1] = bb1;
    }
    __syncthreads();

    float acc[4][4][4];
    #pragma unroll
    for (int mt = 0; mt < 4; mt++)
        #pragma unroll
        for (int nt = 0; nt < 4; nt++)
            #pragma unroll
            for (int i = 0; i < 4; i++) acc[mt][nt][i] = 0.f;

    int buf = 0;
    for (int k0 = 0; k0 < K; k0 += 16) {
        const bool nxt = (k0 + 16) < K;
        if (nxt) {
            const int kn = k0 + 16;
            a0r = *(const float4*)(A + (size_t)(bm + ar) * K + kn + ac4 * 4);
            a1r = *(const float4*)(A + (size_t)(bm + ar + 64) * K + kn + ac4 * 4);
            b0r = *(const float4*)(Bm + (size_t)(kn + br) * N + bn + bc4 * 4);
            b1r = *(const float4*)(Bm + (size_t)(kn + br + 8) * N + bn + bc4 * 4);
        }
        const uint32_t bufOff = (uint32_t)buf * 8192u;   // bytes per A buffer
        #pragma unroll
        for (int ks = 0; ks < 16; ks += 8) {
            // A fragments: one LDSM.x4 per mt tile, literal mt offset (+1024B)
            const uint32_t aBaseAddr = (ks == 0 ? aLd0 : aLd8) + bufOff;
            uint32_t af[4][4];
            #pragma unroll
            for (int mt = 0; mt < 4; mt++)
                ldsm_x4(af[mt], aBaseAddr + mt * 1024u);

            // B fragments: literal-offset scalar LDS (swizzled layout)
            const int x0 = (ks == 0) ? 0 : 16;
            const int x1 = x0 + 8;
            const uint32_t* B0 = &Bs[buf][(ks + tig) * 136]     + nBase;
            const uint32_t* B1 = &Bs[buf][(ks + 4 + tig) * 136] + nBase;
            uint32_t bf[4][2];
            #pragma unroll
            for (int nt = 0; nt < 4; nt++) {
                bf[nt][0] = B0[(nt * 8) ^ x0];
                bf[nt][1] = B1[(nt * 8) ^ x1];
            }
            #pragma unroll
            for (int mt = 0; mt < 4; mt++)
                #pragma unroll
                for (int nt = 0; nt < 4; nt++)
                    mma_tf32(acc[mt][nt], af[mt], bf[nt][0], bf[nt][1]);
        }
        if (nxt) {
            const int nb = buf ^ 1;
            uint4 aa0 = { f2tf(a0r.x), f2tf(a0r.y), f2tf(a0r.z), f2tf(a0r.w) };
            uint4 aa1 = { f2tf(a1r.x), f2tf(a1r.y), f2tf(a1r.z), f2tf(a1r.w) };
            *(uint4*)&As[nb][aSt0] = aa0;
            *(uint4*)&As[nb][aSt1] = aa1;
            uint4 bb0 = { f2tf(b0r.x), f2tf(b0r.y), f2tf(b0r.z), f2tf(b0r.w) };
            uint4 bb1 = { f2tf(b1r.x), f2tf(b1r.y), f2tf(b1r.z), f2tf(b1r.w) };
            *(uint4*)&Bs[nb][bSt0] = bb0;
            *(uint4*)&Bs[nb][bSt1] = bb1;
        }
        __syncthreads();
        buf ^= 1;
    }

    // epilogue: bias + store
    #pragma unroll
    for (int mt = 0; mt < 4; mt++) {
        const int row = bm + wm * 64 + mt * 16 + g;
        #pragma unroll
        for (int nt = 0; nt < 4; nt++) {
            const int col = bn + wn * 32 + nt * 8 + 2 * tig;
            const float bv0 = __ldg(bias + col), bv1 = __ldg(bias + col + 1);
            float2 v0 = { acc[mt][nt][0] + bv0, acc[mt][nt][1] + bv1 };
            float2 v1 = { acc[mt][nt][2] + bv0, acc[mt][nt][3] + bv1 };
            *(float2*)(C + (size_t)row * N + col) = v0;
            *(float2*)(C + (size_t)(row + 8) * N + col) = v1;
        }
    }
}

// ---------------------------------------------------------------------------
// Causal flash attention, tf32 mma.  One block per (qtile=64, head, batch).
// 4 warps; warp w owns query rows [qt*64 + 16w, +16).  HD = 64.
// Pad 72 (row stride = 8 mod 32 banks) -> conflict-free K, V, P accesses.
// ---------------------------------------------------------------------------
__global__ __launch_bounds__(128)
void attn_tf32(const float* __restrict__ qkv, float* __restrict__ outp)
{
    __shared__ uint32_t Ks[64][72];      // [kv][d] tf32 bits
    __shared__ uint32_t Vs[64][72];      // [kv][d]
    __shared__ uint32_t Ps[4][16][72];   // per-warp P slice [qrow][kv]

    const int tid  = threadIdx.x;
    const int w    = tid >> 5;
    const int lane = tid & 31;
    const int g    = lane >> 2;
    const int tig  = lane & 3;
    const int qt   = blockIdx.x;
    const int h    = blockIdx.y;
    const int b    = blockIdx.z;

    const size_t rs = 3 * NE;
    const float* base = qkv + (size_t)b * NS * rs;
    const float* qptr = base + h * NHD;
    const float* kptr = base + NE + h * NHD;
    const float* vptr = base + 2 * NE + h * NHD;

    const int qrow0 = qt * 64 + w * 16;

    // Q fragments (scaled by 1/sqrt(HD) = 0.125), kept in registers for all iters
    uint32_t qf[8][4];
    #pragma unroll
    for (int kt = 0; kt < 8; kt++) {
        const float* r0 = qptr + (size_t)(qrow0 + g) * rs + kt * 8;
        const float* r1 = qptr + (size_t)(qrow0 + g + 8) * rs + kt * 8;
        qf[kt][0] = f2tf(0.125f * __ldg(r0 + tig));
        qf[kt][1] = f2tf(0.125f * __ldg(r1 + tig));
        qf[kt][2] = f2tf(0.125f * __ldg(r0 + tig + 4));
        qf[kt][3] = f2tf(0.125f * __ldg(r1 + tig + 4));
    }

    float o[8][4];
    #pragma unroll
    for (int nt = 0; nt < 8; nt++)
        #pragma unroll
        for (int i = 0; i < 4; i++) o[nt][i] = 0.f;
    float m0 = -INFINITY, m1 = -INFINITY;
    float l0 = 0.f, l1 = 0.f;

    for (int j = 0; j <= qt; j++) {
        __syncthreads();   // guard K/V overwrite vs previous iter reads
        #pragma unroll
        for (int i = 0; i < 8; i++) {
            const int lin = tid + i * 128;       // 0..1023
            const int r   = lin >> 4;
            const int c4  = lin & 15;
            const float4 kv4 = *(const float4*)(kptr + (size_t)(j * 64 + r) * rs + c4 * 4);
            uint4 kk = { f2tf(kv4.x), f2tf(kv4.y), f2tf(kv4.z), f2tf(kv4.w) };
            *(uint4*)&Ks[r][c4 * 4] = kk;
            const float4 vv4 = *(const float4*)(vptr + (size_t)(j * 64 + r) * rs + c4 * 4);
            uint4 vv = { f2tf(vv4.x), f2tf(vv4.y), f2tf(vv4.z), f2tf(vv4.w) };
            *(uint4*)&Vs[r][c4 * 4] = vv;
        }
        __syncthreads();

        // scores S = Q @ K^T   (per warp: 16 x 64)
        float sc[8][4];
        #pragma unroll
        for (int nt = 0; nt < 8; nt++)
            #pragma unroll
            for (int i = 0; i < 4; i++) sc[nt][i] = 0.f;
        #pragma unroll
        for (int kt = 0; kt < 8; kt++) {
            #pragma unroll
            for (int nt = 0; nt < 8; nt++) {
                const uint32_t bb0 = Ks[nt * 8 + g][kt * 8 + tig];
                const uint32_t bb1 = Ks[nt * 8 + g][kt * 8 + tig + 4];
                mma_tf32(sc[nt], qf[kt], bb0, bb1);
            }
        }

        if (j == qt) {   // diagonal tile: elementwise causal mask
            const int r0g = qrow0 + g, r1g = qrow0 + g + 8;
            #pragma unroll
            for (int nt = 0; nt < 8; nt++) {
                const int col = j * 64 + nt * 8 + 2 * tig;
                if (col     > r0g) sc[nt][0] = -1e30f;
                if (col + 1 > r0g) sc[nt][1] = -1e30f;
                if (col     > r1g) sc[nt][2] = -1e30f;
                if (col + 1 > r1g) sc[nt][3] = -1e30f;
            }
        }

        // online softmax (per row-half; rows g and g+8 within warp slice)
        float mt0 = -1e30f, mt1 = -1e30f;
        #pragma unroll
        for (int nt = 0; nt < 8; nt++) {
            mt0 = fmaxf(mt0, fmaxf(sc[nt][0], sc[nt][1]));
            mt1 = fmaxf(mt1, fmaxf(sc[nt][2], sc[nt][3]));
        }
        mt0 = fmaxf(mt0, __shfl_xor_sync(0xffffffffu, mt0, 1));
        mt0 = fmaxf(mt0, __shfl_xor_sync(0xffffffffu, mt0, 2));
        mt1 = fmaxf(mt1, __shfl_xor_sync(0xffffffffu, mt1, 1));
        mt1 = fmaxf(mt1, __shfl_xor_sync(0xffffffffu, mt1, 2));

        const float mn0 = fmaxf(m0, mt0), mn1 = fmaxf(m1, mt1);
        const float al0 = __expf(m0 - mn0), al1 = __expf(m1 - mn1);
        m0 = mn0; m1 = mn1;

        float rs0 = 0.f, rs1 = 0.f;
        #pragma unroll
        for (int nt = 0; nt < 8; nt++) {
            const float p0 = __expf(sc[nt][0] - mn0);
            const float p1 = __expf(sc[nt][1] - mn0);
            const float p2 = __expf(sc[nt][2] - mn1);
            const float p3 = __expf(sc[nt][3] - mn1);
            rs0 += p0 + p1;
            rs1 += p2 + p3;
            uint2 pv0 = { f2tf(p0), f2tf(p1) };
            uint2 pv1 = { f2tf(p2), f2tf(p3) };
            *(uint2*)&Ps[w][g][nt * 8 + 2 * tig]     = pv0;
            *(uint2*)&Ps[w][g + 8][nt * 8 + 2 * tig] = pv1;
            o[nt][0] *= al0; o[nt][1] *= al0;
            o[nt][2] *= al1; o[nt][3] *= al1;
        }
        rs0 += __shfl_xor_sync(0xffffffffu, rs0, 1);
        rs0 += __shfl_xor_sync(0xffffffffu, rs0, 2);
        rs1 += __shfl_xor_sync(0xffffffffu, rs1, 1);
        rs1 += __shfl_xor_sync(0xffffffffu, rs1, 2);
        l0 = l0 * al0 + rs0;
        l1 = l1 * al1 + rs1;

        __syncwarp();

        // O += P @ V
        #pragma unroll
        for (int kt = 0; kt < 8; kt++) {
            uint32_t af[4] = { Ps[w][g][kt * 8 + tig],     Ps[w][g + 8][kt * 8 + tig],
                               Ps[w][g][kt * 8 + tig + 4], Ps[w][g + 8][kt * 8 + tig + 4] };
            #pragma unroll
            for (int nt = 0; nt < 8; nt++) {
                mma_tf32(o[nt], af, Vs[kt * 8 + tig][nt * 8 + g],
                                    Vs[kt * 8 + tig + 4][nt * 8 + g]);
            }
        }
        __syncwarp();
    }

    const float inv0 = 1.f / l0, inv1 = 1.f / l1;
    const size_t orow0 = (size_t)b * NS + qrow0 + g;
    #pragma unroll
    for (int nt = 0; nt < 8; nt++) {
        const int col = h * NHD + nt * 8 + 2 * tig;
        float2 v0 = { o[nt][0] * inv0, o[nt][1] * inv0 };
        float2 v1 = { o[nt][2] * inv1, o[nt][3] * inv1 };
        *(float2*)(outp + orow0 * NE + col) = v0;
        *(float2*)(outp + (orow0 + 8) * NE + col) = v1;
    }
}

// ---------------------------------------------------------------------------
extern "C" void kernel_launch(void* const* d_in, const int* in_sizes, int n_in,
                              void* d_out, int out_size)
{
    (void)in_sizes; (void)n_in; (void)out_size;
    const float* Q  = (const float*)d_in[0];
    const float* Wp = (const float*)d_in[1];
    const float* bp = (const float*)d_in[2];
    const float* Wo = (const float*)d_in[3];
    const float* bo = (const float*)d_in[4];
    float* out = (float*)d_out;

    void* qkv_p = nullptr; void* attn_p = nullptr;
    cudaGetSymbolAddress(&qkv_p, g_qkv);
    cudaGetSymbolAddress(&attn_p, g_attn);
    float* qkv  = (float*)qkv_p;
    float* attn = (float*)attn_p;

    const int M = NB * NS;  // 8192
    gemm_bias_tf32<<<dim3((3 * NE) / 128, M / 128), 256>>>(Q, Wp, bp, qkv, M, 3 * NE, NE);
    attn_tf32<<<dim3(NS / 64, NH, NB), 128>>>(qkv, attn);
    gemm_bias_tf32<<<dim3(NE / 128, M / 128), 256>>>(attn, Wo, bo, out, M, NE, NE);
}

// round 11
// speedup vs baseline: 1.1860x; 1.0099x over previous
#include <cuda_runtime.h>
#include <cstdint>
#include <math.h>

#define NB 4
#define NS 2048
#define NE 1024
#define NH 16
#define NHD 64

// Scratch (allocation-free rules: __device__ globals)
__device__ __align__(256) float g_qkv[(size_t)NB * NS * 3 * NE];   // [B*S, 3E]
__device__ __align__(256) float g_attn[(size_t)NB * NS * NE];      // [B*S, E] joined layout

__device__ __forceinline__ uint32_t f2tf(float x) {
    uint32_t r;
    asm("cvt.rna.tf32.f32 %0, %1;" : "=r"(r) : "f"(x));
    return r;
}

__device__ __forceinline__ void mma_tf32(float* c, const uint32_t* a, uint32_t b0, uint32_t b1) {
    asm volatile(
        "mma.sync.aligned.m16n8k8.row.col.f32.tf32.tf32.f32 "
        "{%0,%1,%2,%3},{%4,%5,%6,%7},{%8,%9},{%0,%1,%2,%3};\n"
        : "+f"(c[0]), "+f"(c[1]), "+f"(c[2]), "+f"(c[3])
        : "r"(a[0]), "r"(a[1]), "r"(a[2]), "r"(a[3]), "r"(b0), "r"(b1));
}

__device__ __forceinline__ void ldsm_x4(uint32_t* r, uint32_t addr) {
    asm volatile("ldmatrix.sync.aligned.m8n8.x4.shared.b16 {%0,%1,%2,%3}, [%4];"
        : "=r"(r[0]), "=r"(r[1]), "=r"(r[2]), "=r"(r[3]) : "r"(addr));
}

__device__ __forceinline__ uint32_t smem_u32(const void* p) {
    return (uint32_t)__cvta_generic_to_shared(p);
}

// Permuted-atom tile layout (words): row r 0..127, c = 16B chunk 0..3.
// 2-row atoms of 32 words; slot permutation XOR (r>>1)&7 makes STS.128
// phases, LDSM 8-row reads, and transposed STS.128 all conflict-free.
__device__ __forceinline__ int a_off(int m, int c) {
    return ((m >> 1) * 32) + 4 * ((((m & 1) << 2) + c) ^ ((m >> 1) & 7));
}

// ---------------------------------------------------------------------------
// C[M,N] = A[M,K] @ B[K,N] + bias   (row-major, tf32 mma, fp32 accumulate)
// Block tile 128x128, K-tile 16, 256 threads = 8 warps (2x4), warp tile 64x32.
// Double-buffered smem.  A fragments via ldmatrix.x4 on [m][k] permuted tile;
// B fragments via ldmatrix.x4 on TRANSPOSED [n][k] permuted tile (B operand
// distribution = A-style distribution of Bt).  All addrs loop-invariant.
// ---------------------------------------------------------------------------
__global__ __launch_bounds__(256, 2)
void gemm_bias_tf32(const float* __restrict__ A, const float* __restrict__ Bm,
                    const float* __restrict__ bias, float* __restrict__ C,
                    int M, int N, int K)
{
    __shared__ uint32_t As[2][2048];   // [m][k-chunk] permuted (8KB/buf)
    __shared__ uint32_t Bt[2][2048];   // [n][k-chunk] permuted (8KB/buf)

    const int tid  = threadIdx.x;
    const int w    = tid >> 5;
    const int lane = tid & 31;
    const int g    = lane >> 2;
    const int tig  = lane & 3;
    const int wm   = w >> 2;           // 0..1
    const int wn   = w & 3;            // 0..3
    const int bm   = blockIdx.y * 128;
    const int bn   = blockIdx.x * 128;

    // A global-load mapping (row-vectorized float4)
    const int ar  = tid >> 2;          // A rows: ar, ar+64
    const int ac4 = tid & 3;           // A cols: ac4*4 .. +3
    const int aSt0 = a_off(ar, ac4);
    const int aSt1 = a_off(ar + 64, ac4);

    // B global-load mapping (column k-quads, coalesced LDG.32 across lanes)
    const int bnl = tid & 127;         // n within tile
    const int bkc = tid >> 7;          // chunks bkc and bkc+2
    const float* Bcol = Bm + (size_t)bn + bnl;
    const int bStA = a_off(bnl, bkc);
    const int bStB = a_off(bnl, bkc + 2);

    // ldmatrix A source addresses (loop-invariant)
    const int lm = (((lane >> 3) & 1) << 3) + (lane & 7);
    const int lc = lane >> 4;
    const int mA = wm * 64 + lm;
    const uint32_t aLd0 = smem_u32(&As[0][a_off(mA, 0 + lc)]);  // ks = 0
    const uint32_t aLd8 = smem_u32(&As[0][a_off(mA, 2 + lc)]);  // ks = 8

    // ldmatrix B source addresses (loop-invariant):
    // matrices: (nt rows, chunk c), (nt rows, c+1), (nt+8 rows? no: +8 rows, c), (+8, c+1)
    const int bRow = wn * 32 + (((lane >> 4) & 1) << 3) + (lane & 7);
    const int bCk  = (lane >> 3) & 1;
    const uint32_t bLd0 = smem_u32(&Bt[0][a_off(bRow, bCk)]);      // ks = 0
    const uint32_t bLd8 = smem_u32(&Bt[0][a_off(bRow, bCk + 2)]);  // ks = 8

    float4 a0r, a1r;
    float bv[8];

    // prologue: load + store k0 = 0 into buffer 0
    {
        a0r = *(const float4*)(A + (size_t)(bm + ar) * K + ac4 * 4);
        a1r = *(const float4*)(A + (size_t)(bm + ar + 64) * K + ac4 * 4);
        #pragma unroll
        for (int j = 0; j < 4; j++) {
            bv[j]     = Bcol[(size_t)(bkc * 4 + j) * N];
            bv[4 + j] = Bcol[(size_t)(bkc * 4 + 8 + j) * N];
        }
        uint4 aa0 = { f2tf(a0r.x), f2tf(a0r.y), f2tf(a0r.z), f2tf(a0r.w) };
        uint4 aa1 = { f2tf(a1r.x), f2tf(a1r.y), f2tf(a1r.z), f2tf(a1r.w) };
        *(uint4*)&As[0][aSt0] = aa0;
        *(uint4*)&As[0][aSt1] = aa1;
        uint4 bb0 = { f2tf(bv[0]), f2tf(bv[1]), f2tf(bv[2]), f2tf(bv[3]) };
        uint4 bb1 = { f2tf(bv[4]), f2tf(bv[5]), f2tf(bv[6]), f2tf(bv[7]) };
        *(uint4*)&Bt[0][bStA] = bb0;
        *(uint4*)&Bt[0][bStB] = bb1;
    }
    __syncthreads();

    float acc[4][4][4];
    #pragma unroll
    for (int mt = 0; mt < 4; mt++)
        #pragma unroll
        for (int nt = 0; nt < 4; nt++)
            #pragma unroll
            for (int i = 0; i < 4; i++) acc[mt][nt][i] = 0.f;

    int buf = 0;
    for (int k0 = 0; k0 < K; k0 += 16) {
        const bool nxt = (k0 + 16) < K;
        if (nxt) {
            const int kn = k0 + 16;
            a0r = *(const float4*)(A + (size_t)(bm + ar) * K + kn + ac4 * 4);
            a1r = *(const float4*)(A + (size_t)(bm + ar + 64) * K + kn + ac4 * 4);
            #pragma unroll
            for (int j = 0; j < 4; j++) {
                bv[j]     = Bcol[(size_t)(kn + bkc * 4 + j) * N];
                bv[4 + j] = Bcol[(size_t)(kn + bkc * 4 + 8 + j) * N];
            }
        }
        const uint32_t bufOff = (uint32_t)buf * 8192u;   // bytes per buffer
        #pragma unroll
        for (int ks = 0; ks < 16; ks += 8) {
            const uint32_t aAddr = (ks == 0 ? aLd0 : aLd8) + bufOff;
            const uint32_t bAddr = (ks == 0 ? bLd0 : bLd8) + bufOff;
            uint32_t af[4][4];
            #pragma unroll
            for (int mt = 0; mt < 4; mt++)
                ldsm_x4(af[mt], aAddr + mt * 1024u);
            // B: x4 #1 -> nt 0,1 ; x4 #2 (+16 n rows = +1024B) -> nt 2,3
            uint32_t bq0[4], bq1[4];
            ldsm_x4(bq0, bAddr);
            ldsm_x4(bq1, bAddr + 1024u);
            #pragma unroll
            for (int mt = 0; mt < 4; mt++) {
                mma_tf32(acc[mt][0], af[mt], bq0[0], bq0[1]);
                mma_tf32(acc[mt][1], af[mt], bq0[2], bq0[3]);
                mma_tf32(acc[mt][2], af[mt], bq1[0], bq1[1]);
                mma_tf32(acc[mt][3], af[mt], bq1[2], bq1[3]);
            }
        }
        if (nxt) {
            const int nb = buf ^ 1;
            uint4 aa0 = { f2tf(a0r.x), f2tf(a0r.y), f2tf(a0r.z), f2tf(a0r.w) };
            uint4 aa1 = { f2tf(a1r.x), f2tf(a1r.y), f2tf(a1r.z), f2tf(a1r.w) };
            *(uint4*)&As[nb][aSt0] = aa0;
            *(uint4*)&As[nb][aSt1] = aa1;
            uint4 bb0 = { f2tf(bv[0]), f2tf(bv[1]), f2tf(bv[2]), f2tf(bv[3]) };
            uint4 bb1 = { f2tf(bv[4]), f2tf(bv[5]), f2tf(bv[6]), f2tf(bv[7]) };
            *(uint4*)&Bt[nb][bStA] = bb0;
            *(uint4*)&Bt[nb][bStB] = bb1;
        }
        __syncthreads();
        buf ^= 1;
    }

    // epilogue: bias + store
    #pragma unroll
    for (int mt = 0; mt < 4; mt++) {
        const int row = bm + wm * 64 + mt * 16 + g;
        #pragma unroll
        for (int nt = 0; nt < 4; nt++) {
            const int col = bn + wn * 32 + nt * 8 + 2 * tig;
            const float bv0 = __ldg(bias + col), bv1 = __ldg(bias + col + 1);
            float2 v0 = { acc[mt][nt][0] + bv0, acc[mt][nt][1] + bv1 };
            float2 v1 = { acc[mt][nt][2] + bv0, acc[mt][nt][3] + bv1 };
            *(float2*)(C + (size_t)row * N + col) = v0;
            *(float2*)(C + (size_t)(row + 8) * N + col) = v1;
        }
    }
}

// ---------------------------------------------------------------------------
// Causal flash attention, tf32 mma.  One block per (qtile=64, head, batch).
// 4 warps; warp w owns query rows [qt*64 + 16w, +16).  HD = 64.
// Pad 72 (row stride = 8 mod 32 banks) -> conflict-free K, V, P accesses.
// ---------------------------------------------------------------------------
__global__ __launch_bounds__(128)
void attn_tf32(const float* __restrict__ qkv, float* __restrict__ outp)
{
    __shared__ uint32_t Ks[64][72];      // [kv][d] tf32 bits
    __shared__ uint32_t Vs[64][72];      // [kv][d]
    __shared__ uint32_t Ps[4][16][72];   // per-warp P slice [qrow][kv]

    const int tid  = threadIdx.x;
    const int w    = tid >> 5;
    const int lane = tid & 31;
    const int g    = lane >> 2;
    const int tig  = lane & 3;
    const int qt   = blockIdx.x;
    const int h    = blockIdx.y;
    const int b    = blockIdx.z;

    const size_t rs = 3 * NE;
    const float* base = qkv + (size_t)b * NS * rs;
    const float* qptr = base + h * NHD;
    const float* kptr = base + NE + h * NHD;
    const float* vptr = base + 2 * NE + h * NHD;

    const int qrow0 = qt * 64 + w * 16;

    // Q fragments (scaled by 1/sqrt(HD) = 0.125), kept in registers for all iters
    uint32_t qf[8][4];
    #pragma unroll
    for (int kt = 0; kt < 8; kt++) {
        const float* r0 = qptr + (size_t)(qrow0 + g) * rs + kt * 8;
        const float* r1 = qptr + (size_t)(qrow0 + g + 8) * rs + kt * 8;
        qf[kt][0] = f2tf(0.125f * __ldg(r0 + tig));
        qf[kt][1] = f2tf(0.125f * __ldg(r1 + tig));
        qf[kt][2] = f2tf(0.125f * __ldg(r0 + tig + 4));
        qf[kt][3] = f2tf(0.125f * __ldg(r1 + tig + 4));
    }

    float o[8][4];
    #pragma unroll
    for (int nt = 0; nt < 8; nt++)
        #pragma unroll
        for (int i = 0; i < 4; i++) o[nt][i] = 0.f;
    float m0 = -INFINITY, m1 = -INFINITY;
    float l0 = 0.f, l1 = 0.f;

    for (int j = 0; j <= qt; j++) {
        __syncthreads();   // guard K/V overwrite vs previous iter reads
        #pragma unroll
        for (int i = 0; i < 8; i++) {
            const int lin = tid + i * 128;       // 0..1023
            const int r   = lin >> 4;
            const int c4  = lin & 15;
            const float4 kv4 = *(const float4*)(kptr + (size_t)(j * 64 + r) * rs + c4 * 4);
            uint4 kk = { f2tf(kv4.x), f2tf(kv4.y), f2tf(kv4.z), f2tf(kv4.w) };
            *(uint4*)&Ks[r][c4 * 4] = kk;
            const float4 vv4 = *(const float4*)(vptr + (size_t)(j * 64 + r) * rs + c4 * 4);
            uint4 vv = { f2tf(vv4.x), f2tf(vv4.y), f2tf(vv4.z), f2tf(vv4.w) };
            *(uint4*)&Vs[r][c4 * 4] = vv;
        }
        __syncthreads();

        // scores S = Q @ K^T   (per warp: 16 x 64)
        float sc[8][4];
        #pragma unroll
        for (int nt = 0; nt < 8; nt++)
            #pragma unroll
            for (int i = 0; i < 4; i++) sc[nt][i] = 0.f;
        #pragma unroll
        for (int kt = 0; kt < 8; kt++) {
            #pragma unroll
            for (int nt = 0; nt < 8; nt++) {
                const uint32_t bb0 = Ks[nt * 8 + g][kt * 8 + tig];
                const uint32_t bb1 = Ks[nt * 8 + g][kt * 8 + tig + 4];
                mma_tf32(sc[nt], qf[kt], bb0, bb1);
            }
        }

        if (j == qt) {   // diagonal tile: elementwise causal mask
            const int r0g = qrow0 + g, r1g = qrow0 + g + 8;
            #pragma unroll
            for (int nt = 0; nt < 8; nt++) {
                const int col = j * 64 + nt * 8 + 2 * tig;
                if (col     > r0g) sc[nt][0] = -1e30f;
                if (col + 1 > r0g) sc[nt][1] = -1e30f;
                if (col     > r1g) sc[nt][2] = -1e30f;
                if (col + 1 > r1g) sc[nt][3] = -1e30f;
            }
        }

        // online softmax (per row-half; rows g and g+8 within warp slice)
        float mt0 = -1e30f, mt1 = -1e30f;
        #pragma unroll
        for (int nt = 0; nt < 8; nt++) {
            mt0 = fmaxf(mt0, fmaxf(sc[nt][0], sc[nt][1]));
            mt1 = fmaxf(mt1, fmaxf(sc[nt][2], sc[nt][3]));
        }
        mt0 = fmaxf(mt0, __shfl_xor_sync(0xffffffffu, mt0, 1));
        mt0 = fmaxf(mt0, __shfl_xor_sync(0xffffffffu, mt0, 2));
        mt1 = fmaxf(mt1, __shfl_xor_sync(0xffffffffu, mt1, 1));
        mt1 = fmaxf(mt1, __shfl_xor_sync(0xffffffffu, mt1, 2));

        const float mn0 = fmaxf(m0, mt0), mn1 = fmaxf(m1, mt1);
        const float al0 = __expf(m0 - mn0), al1 = __expf(m1 - mn1);
        m0 = mn0; m1 = mn1;

        float rs0 = 0.f, rs1 = 0.f;
        #pragma unroll
        for (int nt = 0; nt < 8; nt++) {
            const float p0 = __expf(sc[nt][0] - mn0);
            const float p1 = __expf(sc[nt][1] - mn0);
            const float p2 = __expf(sc[nt][2] - mn1);
            const float p3 = __expf(sc[nt][3] - mn1);
            rs0 += p0 + p1;
            rs1 += p2 + p3;
            uint2 pv0 = { f2tf(p0), f2tf(p1) };
            uint2 pv1 = { f2tf(p2), f2tf(p3) };
            *(uint2*)&Ps[w][g][nt * 8 + 2 * tig]     = pv0;
            *(uint2*)&Ps[w][g + 8][nt * 8 + 2 * tig] = pv1;
            o[nt][0] *= al0; o[nt][1] *= al0;
            o[nt][2] *= al1; o[nt][3] *= al1;
        }
        rs0 += __shfl_xor_sync(0xffffffffu, rs0, 1);
        rs0 += __shfl_xor_sync(0xffffffffu, rs0, 2);
        rs1 += __shfl_xor_sync(0xffffffffu, rs1, 1);
        rs1 += __shfl_xor_sync(0xffffffffu, rs1, 2);
        l0 = l0 * al0 + rs0;
        l1 = l1 * al1 + rs1;

        __syncwarp();

        // O += P @ V
        #pragma unroll
        for (int kt = 0; kt < 8; kt++) {
            uint32_t af[4] = { Ps[w][g][kt * 8 + tig],     Ps[w][g + 8][kt * 8 + tig],
                               Ps[w][g][kt * 8 + tig + 4], Ps[w][g + 8][kt * 8 + tig + 4] };
            #pragma unroll
            for (int nt = 0; nt < 8; nt++) {
                mma_tf32(o[nt], af, Vs[kt * 8 + tig][nt * 8 + g],
                                    Vs[kt * 8 + tig + 4][nt * 8 + g]);
            }
        }
        __syncwarp();
    }

    const float inv0 = 1.f / l0, inv1 = 1.f / l1;
    const size_t orow0 = (size_t)b * NS + qrow0 + g;
    #pragma unroll
    for (int nt = 0; nt < 8; nt++) {
        const int col = h * NHD + nt * 8 + 2 * tig;
        float2 v0 = { o[nt][0] * inv0, o[nt][1] * inv0 };
        float2 v1 = { o[nt][2] * inv1, o[nt][3] * inv1 };
        *(float2*)(outp + orow0 * NE + col) = v0;
        *(float2*)(outp + (orow0 + 8) * NE + col) = v1;
    }
}

// ---------------------------------------------------------------------------
extern "C" void kernel_launch(void* const* d_in, const int* in_sizes, int n_in,
                              void* d_out, int out_size)
{
    (void)in_sizes; (void)n_in; (void)out_size;
    const float* Q  = (const float*)d_in[0];
    const float* Wp = (const float*)d_in[1];
    const float* bp = (const float*)d_in[2];
    const float* Wo = (const float*)d_in[3];
    const float* bo = (const float*)d_in[4];
    float* out = (float*)d_out;

    void* qkv_p = nullptr; void* attn_p = nullptr;
    cudaGetSymbolAddress(&qkv_p, g_qkv);
    cudaGetSymbolAddress(&attn_p, g_attn);
    float* qkv  = (float*)qkv_p;
    float* attn = (float*)attn_p;

    const int M = NB * NS;  // 8192
    gemm_bias_tf32<<<dim3((3 * NE) / 128, M / 128), 256>>>(Q, Wp, bp, qkv, M, 3 * NE, NE);
    attn_tf32<<<dim3(NS / 64, NH, NB), 128>>>(qkv, attn);
    gemm_bias_tf32<<<dim3(NE / 128, M / 128), 256>>>(attn, Wo, bo, out, M, NE, NE);
}

// round 12
// speedup vs baseline: 1.7932x; 1.5120x over previous
#include <cuda_runtime.h>
#include <cuda_fp16.h>
#include <cstdint>
#include <math.h>

#define NB 4
#define NS 2048
#define NE 1024
#define NH 16
#define NHD 64

// Scratch (allocation-free rules: __device__ globals)
__device__ __align__(256) float g_qkv[(size_t)NB * NS * 3 * NE];   // [B*S, 3E]
__device__ __align__(256) float g_attn[(size_t)NB * NS * NE];      // [B*S, E] joined layout

__device__ __forceinline__ uint32_t f2h2(float lo, float hi) {
    __half2 h = __floats2half2_rn(lo, hi);   // .x = lo (low half), .y = hi
    return *(uint32_t*)&h;
}

// D(f32) += A(f16,4regs) * B(f16,2regs)
__device__ __forceinline__ void mma_f16(float* c, const uint32_t* a, uint32_t b0, uint32_t b1) {
    asm volatile(
        "mma.sync.aligned.m16n8k16.row.col.f32.f16.f16.f32 "
        "{%0,%1,%2,%3},{%4,%5,%6,%7},{%8,%9},{%0,%1,%2,%3};\n"
        : "+f"(c[0]), "+f"(c[1]), "+f"(c[2]), "+f"(c[3])
        : "r"(a[0]), "r"(a[1]), "r"(a[2]), "r"(a[3]), "r"(b0), "r"(b1));
}

__device__ __forceinline__ void ldsm_x4(uint32_t* r, uint32_t addr) {
    asm volatile("ldmatrix.sync.aligned.m8n8.x4.shared.b16 {%0,%1,%2,%3}, [%4];"
        : "=r"(r[0]), "=r"(r[1]), "=r"(r[2]), "=r"(r[3]) : "r"(addr));
}
__device__ __forceinline__ void ldsm_x4_t(uint32_t* r, uint32_t addr) {
    asm volatile("ldmatrix.sync.aligned.m8n8.x4.trans.shared.b16 {%0,%1,%2,%3}, [%4];"
        : "=r"(r[0]), "=r"(r[1]), "=r"(r[2]), "=r"(r[3]) : "r"(addr));
}

__device__ __forceinline__ uint32_t smem_u32(const void* p) {
    return (uint32_t)__cvta_generic_to_shared(p);
}

// GEMM tile layout (words): 128 rows x 16 halves (2 chunks of 16B per row).
// 4-row/128B atoms, slot = ((r&3)*2 + c) ^ ((r>>2)&7).  STS.128 phases and
// LDSM 8-row reads both tile all banks (hand-checked).
__device__ __forceinline__ int a_off16(int r, int c) {
    return ((r >> 2) * 32) + 4 * ((((r & 3) << 1) + c) ^ ((r >> 2) & 7));
}

// Attention K/V tile layout (words): 64 rows x 64 halves (8 chunks of 16B).
// Swizzle chunk ^ (row&7); LDSM addr decomposes as (base + row*2048)^(kt<<5).
__device__ __forceinline__ int k_off(int r, int c) {
    return r * 32 + ((c ^ (r & 7)) << 2);
}

// ---------------------------------------------------------------------------
// C[M,N] = A[M,K] @ B[K,N] + bias   (fp16 mma m16n8k16, fp32 accumulate)
// Block tile 128x128, K-tile 16, 256 threads = 8 warps (2x4), warp tile 64x32.
// Double-buffered fp16 smem tiles; A and Bt (transposed) both via ldmatrix.x4.
// ---------------------------------------------------------------------------
__global__ __launch_bounds__(256, 2)
void gemm_bias_f16(const float* __restrict__ A, const float* __restrict__ Bm,
                   const float* __restrict__ bias, float* __restrict__ C,
                   int M, int N, int K)
{
    __shared__ uint32_t As[2][1024];   // [m 128][k 16 halves] permuted, 4KB/buf
    __shared__ uint32_t Bt[2][1024];   // [n 128][k 16 halves] permuted, 4KB/buf

    const int tid  = threadIdx.x;
    const int w    = tid >> 5;
    const int lane = tid & 31;
    const int g    = lane >> 2;
    const int tig  = lane & 3;
    const int wm   = w >> 2;           // 0..1
    const int wn   = w & 3;            // 0..3
    const int bm   = blockIdx.y * 128;
    const int bn   = blockIdx.x * 128;

    // A global-load mapping: row = tid>>1 (0..127), 8 floats = chunk tid&1
    const int arow = tid >> 1;
    const int ack  = tid & 1;
    const float* Arow = A + (size_t)(bm + arow) * K + ack * 8;
    const int aSt = a_off16(arow, ack);

    // B global-load mapping: n = tid&127, k-half = tid>>7 (8 LDG.32 down k)
    const int bnl = tid & 127;
    const int bkh = tid >> 7;
    const float* Bcol = Bm + (size_t)bn + bnl;
    const int bSt = a_off16(bnl, bkh);

    // ldmatrix A addresses (loop-invariant): m0=rows0-7/c0, m1=rows8-15/c0,
    // m2=rows0-7/c1, m3=rows8-15/c1  ->  a0..a3 of m16n8k16.
    const int alr = lane & 15;
    const int alc = lane >> 4;
    uint32_t aAddr[4];
    #pragma unroll
    for (int mt = 0; mt < 4; mt++)
        aAddr[mt] = smem_u32(&As[0][a_off16(wm * 64 + mt * 16 + alr, alc)]);

    // ldmatrix B addresses: m0=(n0-7,c0), m1=(n0-7,c1), m2=(n8-15,c0), m3=(n8-15,c1)
    const int blr = (lane & 7) + ((lane >> 4) << 3);
    const int blc = (lane >> 3) & 1;
    uint32_t bAddr[2];
    #pragma unroll
    for (int h = 0; h < 2; h++)
        bAddr[h] = smem_u32(&Bt[0][a_off16(wn * 32 + h * 16 + blr, blc)]);

    float4 av0, av1;
    float bv[8];

    // prologue k0 = 0 -> buffer 0
    {
        av0 = *(const float4*)(Arow);
        av1 = *(const float4*)(Arow + 4);
        #pragma unroll
        for (int j = 0; j < 8; j++) bv[j] = Bcol[(size_t)(bkh * 8 + j) * N];
        uint4 aa = { f2h2(av0.x, av0.y), f2h2(av0.z, av0.w),
                     f2h2(av1.x, av1.y), f2h2(av1.z, av1.w) };
        *(uint4*)&As[0][aSt] = aa;
        uint4 bb = { f2h2(bv[0], bv[1]), f2h2(bv[2], bv[3]),
                     f2h2(bv[4], bv[5]), f2h2(bv[6], bv[7]) };
        *(uint4*)&Bt[0][bSt] = bb;
    }
    __syncthreads();

    float acc[4][4][4];
    #pragma unroll
    for (int mt = 0; mt < 4; mt++)
        #pragma unroll
        for (int nt = 0; nt < 4; nt++)
            #pragma unroll
            for (int i = 0; i < 4; i++) acc[mt][nt][i] = 0.f;

    int buf = 0;
    for (int k0 = 0; k0 < K; k0 += 16) {
        const bool nxt = (k0 + 16) < K;
        if (nxt) {
            const int kn = k0 + 16;
            av0 = *(const float4*)(Arow + kn);
            av1 = *(const float4*)(Arow + kn + 4);
            #pragma unroll
            for (int j = 0; j < 8; j++) bv[j] = Bcol[(size_t)(kn + bkh * 8 + j) * N];
        }
        const uint32_t bufOff = (uint32_t)buf * 4096u;
        uint32_t af[4][4], bq0[4], bq1[4];
        #pragma unroll
        for (int mt = 0; mt < 4; mt++)
            ldsm_x4(af[mt], aAddr[mt] + bufOff);
        ldsm_x4(bq0, bAddr[0] + bufOff);
        ldsm_x4(bq1, bAddr[1] + bufOff);
        #pragma unroll
        for (int mt = 0; mt < 4; mt++) {
            mma_f16(acc[mt][0], af[mt], bq0[0], bq0[1]);
            mma_f16(acc[mt][1], af[mt], bq0[2], bq0[3]);
            mma_f16(acc[mt][2], af[mt], bq1[0], bq1[1]);
            mma_f16(acc[mt][3], af[mt], bq1[2], bq1[3]);
        }
        if (nxt) {
            const int nb = buf ^ 1;
            uint4 aa = { f2h2(av0.x, av0.y), f2h2(av0.z, av0.w),
                         f2h2(av1.x, av1.y), f2h2(av1.z, av1.w) };
            *(uint4*)&As[nb][aSt] = aa;
            uint4 bb = { f2h2(bv[0], bv[1]), f2h2(bv[2], bv[3]),
                         f2h2(bv[4], bv[5]), f2h2(bv[6], bv[7]) };
            *(uint4*)&Bt[nb][bSt] = bb;
        }
        __syncthreads();
        buf ^= 1;
    }

    // epilogue: bias + store (C fragment layout identical to k8 case)
    #pragma unroll
    for (int mt = 0; mt < 4; mt++) {
        const int row = bm + wm * 64 + mt * 16 + g;
        #pragma unroll
        for (int nt = 0; nt < 4; nt++) {
            const int col = bn + wn * 32 + nt * 8 + 2 * tig;
            const float bv0 = __ldg(bias + col), bv1 = __ldg(bias + col + 1);
            float2 v0 = { acc[mt][nt][0] + bv0, acc[mt][nt][1] + bv1 };
            float2 v1 = { acc[mt][nt][2] + bv0, acc[mt][nt][3] + bv1 };
            *(float2*)(C + (size_t)row * N + col) = v0;
            *(float2*)(C + (size_t)(row + 8) * N + col) = v1;
        }
    }
}

// ---------------------------------------------------------------------------
// Causal flash attention, fp16 mma.  One block per (qtile=64, head, batch).
// 4 warps; warp w owns query rows [qt*64 + 16w, +16).  HD = 64.
// K via ldmatrix (its [kv][d] layout IS the Bt orientation for S=Q@K^T);
// V via ldmatrix.trans; P stays in registers (S C-frag == P A-frag layout).
// ---------------------------------------------------------------------------
__global__ __launch_bounds__(128)
void attn_f16(const float* __restrict__ qkv, float* __restrict__ outp)
{
    __shared__ uint32_t Ks[2048];   // [kv 64][d 64 halves] swizzled, 8KB
    __shared__ uint32_t Vs[2048];   // same layout

    const int tid  = threadIdx.x;
    const int w    = tid >> 5;
    const int lane = tid & 31;
    const int g    = lane >> 2;
    const int tig  = lane & 3;
    const int qt   = blockIdx.x;
    const int h    = blockIdx.y;
    const int b    = blockIdx.z;

    const size_t rs = 3 * NE;
    const float* base = qkv + (size_t)b * NS * rs;
    const float* qptr = base + h * NHD;
    const float* kptr = base + NE + h * NHD;
    const float* vptr = base + 2 * NE + h * NHD;

    const int qrow0 = qt * 64 + w * 16;

    // Q fragments fp16 (scaled by 0.125), 4 k-steps x 4 regs
    uint32_t qf[4][4];
    #pragma unroll
    for (int kt = 0; kt < 4; kt++) {
        const int d0 = kt * 16 + 2 * tig;
        const float* r0 = qptr + (size_t)(qrow0 + g) * rs;
        const float* r1 = qptr + (size_t)(qrow0 + g + 8) * rs;
        qf[kt][0] = f2h2(0.125f * __ldg(r0 + d0),     0.125f * __ldg(r0 + d0 + 1));
        qf[kt][1] = f2h2(0.125f * __ldg(r1 + d0),     0.125f * __ldg(r1 + d0 + 1));
        qf[kt][2] = f2h2(0.125f * __ldg(r0 + d0 + 8), 0.125f * __ldg(r0 + d0 + 9));
        qf[kt][3] = f2h2(0.125f * __ldg(r1 + d0 + 8), 0.125f * __ldg(r1 + d0 + 9));
    }

    // K ldmatrix base: matrices (rows p*8..+7, chunk 2kt) / (.., 2kt+1) / (+8 rows ..)
    const int klr = ((lane >> 4) << 3) + (lane & 7);
    const int klc = (lane >> 3) & 1;
    const uint32_t kBase = smem_u32(&Ks[k_off(klr, klc)]);
    // V ldmatrix.trans base: rows kt*16 + (lane&15), chunk 2p + (lane>>4)
    const int vlr = lane & 15;
    const int vlc = lane >> 4;
    const uint32_t vBase = smem_u32(&Vs[k_off(vlr, vlc)]);

    float o[8][4];
    #pragma unroll
    for (int nt = 0; nt < 8; nt++)
        #pragma unroll
        for (int i = 0; i < 4; i++) o[nt][i] = 0.f;
    float m0 = -INFINITY, m1 = -INFINITY;
    float l0 = 0.f, l1 = 0.f;

    for (int j = 0; j <= qt; j++) {
        __syncthreads();   // guard K/V overwrite vs previous iter reads
        // load K,V tiles: 512 chunks of 16B each; thread handles 4 chunks.
        #pragma unroll
        for (int i = 0; i < 4; i++) {
            const int id = tid + i * 128;     // 0..511
            const int r  = id >> 3;
            const int c  = id & 7;
            const float* kp = kptr + (size_t)(j * 64 + r) * rs + c * 8;
            float4 k0 = *(const float4*)(kp);
            float4 k1 = *(const float4*)(kp + 4);
            uint4 kk = { f2h2(k0.x, k0.y), f2h2(k0.z, k0.w),
                         f2h2(k1.x, k1.y), f2h2(k1.z, k1.w) };
            *(uint4*)&Ks[k_off(r, c)] = kk;
            const float* vp = vptr + (size_t)(j * 64 + r) * rs + c * 8;
            float4 v0 = *(const float4*)(vp);
            float4 v1 = *(const float4*)(vp + 4);
            uint4 vv = { f2h2(v0.x, v0.y), f2h2(v0.z, v0.w),
                         f2h2(v1.x, v1.y), f2h2(v1.z, v1.w) };
            *(uint4*)&Vs[k_off(r, c)] = vv;
        }
        __syncthreads();

        // S = Q @ K^T  (per warp 16 x 64): kt = d/16 step, p = kv 16-col pair
        float sc[8][4];
        #pragma unroll
        for (int nt = 0; nt < 8; nt++)
            #pragma unroll
            for (int i = 0; i < 4; i++) sc[nt][i] = 0.f;
        #pragma unroll
        for (int kt = 0; kt < 4; kt++) {
            #pragma unroll
            for (int p = 0; p < 4; p++) {
                uint32_t bq[4];
                ldsm_x4(bq, (kBase + p * 2048u) ^ ((uint32_t)kt << 5));
                mma_f16(sc[2 * p],     qf[kt], bq[0], bq[1]);
                mma_f16(sc[2 * p + 1], qf[kt], bq[2], bq[3]);
            }
        }

        if (j == qt) {   // diagonal tile: elementwise causal mask
            const int r0g = qrow0 + g, r1g = qrow0 + g + 8;
            #pragma unroll
            for (int nt = 0; nt < 8; nt++) {
                const int col = j * 64 + nt * 8 + 2 * tig;
                if (col     > r0g) sc[nt][0] = -1e30f;
                if (col + 1 > r0g) sc[nt][1] = -1e30f;
                if (col     > r1g) sc[nt][2] = -1e30f;
                if (col + 1 > r1g) sc[nt][3] = -1e30f;
            }
        }

        // online softmax
        float mt0 = -1e30f, mt1 = -1e30f;
        #pragma unroll
        for (int nt = 0; nt < 8; nt++) {
            mt0 = fmaxf(mt0, fmaxf(sc[nt][0], sc[nt][1]));
            mt1 = fmaxf(mt1, fmaxf(sc[nt][2], sc[nt][3]));
        }
        mt0 = fmaxf(mt0, __shfl_xor_sync(0xffffffffu, mt0, 1));
        mt0 = fmaxf(mt0, __shfl_xor_sync(0xffffffffu, mt0, 2));
        mt1 = fmaxf(mt1, __shfl_xor_sync(0xffffffffu, mt1, 1));
        mt1 = fmaxf(mt1, __shfl_xor_sync(0xffffffffu, mt1, 2));

        const float mn0 = fmaxf(m0, mt0), mn1 = fmaxf(m1, mt1);
        const float al0 = __expf(m0 - mn0), al1 = __expf(m1 - mn1);
        m0 = mn0; m1 = mn1;

        // exp, pack P to fp16 A-fragments IN REGISTERS (no smem round trip)
        uint32_t ph[8][2];
        float rs0 = 0.f, rs1 = 0.f;
        #pragma unroll
        for (int nt = 0; nt < 8; nt++) {
            const float p0 = __expf(sc[nt][0] - mn0);
            const float p1 = __expf(sc[nt][1] - mn0);
            const float p2 = __expf(sc[nt][2] - mn1);
            const float p3 = __expf(sc[nt][3] - mn1);
            rs0 += p0 + p1;
            rs1 += p2 + p3;
            ph[nt][0] = f2h2(p0, p1);
            ph[nt][1] = f2h2(p2, p3);
            o[nt][0] *= al0; o[nt][1] *= al0;
            o[nt][2] *= al1; o[nt][3] *= al1;
        }
        rs0 += __shfl_xor_sync(0xffffffffu, rs0, 1);
        rs0 += __shfl_xor_sync(0xffffffffu, rs0, 2);
        rs1 += __shfl_xor_sync(0xffffffffu, rs1, 1);
        rs1 += __shfl_xor_sync(0xffffffffu, rs1, 2);
        l0 = l0 * al0 + rs0;
        l1 = l1 * al1 + rs1;

        // O += P @ V : kt = kv 16-step, p = d 16-col pair (V via ldmatrix.trans)
        #pragma unroll
        for (int kt = 0; kt < 4; kt++) {
            uint32_t pa[4] = { ph[2 * kt][0], ph[2 * kt][1],
                               ph[2 * kt + 1][0], ph[2 * kt + 1][1] };
            #pragma unroll
            for (int p = 0; p < 4; p++) {
                uint32_t vq[4];
                ldsm_x4_t(vq, (vBase + kt * 2048u) ^ ((uint32_t)p << 5));
                mma_f16(o[2 * p],     pa, vq[0], vq[1]);
                mma_f16(o[2 * p + 1], pa, vq[2], vq[3]);
            }
        }
    }

    const float inv0 = 1.f / l0, inv1 = 1.f / l1;
    const size_t orow0 = (size_t)b * NS + qrow0 + g;
    #pragma unroll
    for (int nt = 0; nt < 8; nt++) {
        const int col = h * NHD + nt * 8 + 2 * tig;
        float2 v0 = { o[nt][0] * inv0, o[nt][1] * inv0 };
        float2 v1 = { o[nt][2] * inv1, o[nt][3] * inv1 };
        *(float2*)(outp + orow0 * NE + col) = v0;
        *(float2*)(outp + (orow0 + 8) * NE + col) = v1;
    }
}

// ---------------------------------------------------------------------------
extern "C" void kernel_launch(void* const* d_in, const int* in_sizes, int n_in,
                              void* d_out, int out_size)
{
    (void)in_sizes; (void)n_in; (void)out_size;
    const float* Q  = (const float*)d_in[0];
    const float* Wp = (const float*)d_in[1];
    const float* bp = (const float*)d_in[2];
    const float* Wo = (const float*)d_in[3];
    const float* bo = (const float*)d_in[4];
    float* out = (float*)d_out;

    void* qkv_p = nullptr; void* attn_p = nullptr;
    cudaGetSymbolAddress(&qkv_p, g_qkv);
    cudaGetSymbolAddress(&attn_p, g_attn);
    float* qkv  = (float*)qkv_p;
    float* attn = (float*)attn_p;

    const int M = NB * NS;  // 8192
    gemm_bias_f16<<<dim3((3 * NE) / 128, M / 128), 256>>>(Q, Wp, bp, qkv, M, 3 * NE, NE);
    attn_f16<<<dim3(NS / 64, NH, NB), 128>>>(qkv, attn);
    gemm_bias_f16<<<dim3(NE / 128, M / 128), 256>>>(attn, Wo, bo, out, M, NE, NE);
}

// round 14
// speedup vs baseline: 2.8749x; 1.6033x over previous
#include <cuda_runtime.h>
#include <cuda_fp16.h>
#include <cstdint>
#include <math.h>

#define NB 4
#define NS 2048
#define NE 1024
#define NH 16
#define NHD 64

// Scratch (allocation-free rules: __device__ globals), all fp16
__device__ __align__(256) __half g_Qh[(size_t)NB * NS * NE];
__device__ __align__(256) __half g_Wph[(size_t)NE * 3 * NE];
__device__ __align__(256) __half g_Woh[(size_t)NE * NE];
__device__ __align__(256) __half g_qkvh[(size_t)NB * NS * 3 * NE];
__device__ __align__(256) __half g_attnh[(size_t)NB * NS * NE];

__device__ __forceinline__ uint32_t f2h2(float lo, float hi) {
    __half2 h = __floats2half2_rn(lo, hi);
    return *(uint32_t*)&h;
}

__device__ __forceinline__ void mma_f16(float* c, const uint32_t* a, uint32_t b0, uint32_t b1) {
    asm volatile(
        "mma.sync.aligned.m16n8k16.row.col.f32.f16.f16.f32 "
        "{%0,%1,%2,%3},{%4,%5,%6,%7},{%8,%9},{%0,%1,%2,%3};\n"
        : "+f"(c[0]), "+f"(c[1]), "+f"(c[2]), "+f"(c[3])
        : "r"(a[0]), "r"(a[1]), "r"(a[2]), "r"(a[3]), "r"(b0), "r"(b1));
}

__device__ __forceinline__ void ldsm_x4(uint32_t* r, uint32_t addr) {
    asm volatile("ldmatrix.sync.aligned.m8n8.x4.shared.b16 {%0,%1,%2,%3}, [%4];"
        : "=r"(r[0]), "=r"(r[1]), "=r"(r[2]), "=r"(r[3]) : "r"(addr));
}
__device__ __forceinline__ void ldsm_x4_t(uint32_t* r, uint32_t addr) {
    asm volatile("ldmatrix.sync.aligned.m8n8.x4.trans.shared.b16 {%0,%1,%2,%3}, [%4];"
        : "=r"(r[0]), "=r"(r[1]), "=r"(r[2]), "=r"(r[3]) : "r"(addr));
}

__device__ __forceinline__ uint32_t smem_u32(const void* p) {
    return (uint32_t)__cvta_generic_to_shared(p);
}

__device__ __forceinline__ void cp16(uint32_t dst, const void* src) {
    asm volatile("cp.async.cg.shared.global [%0], [%1], 16;" :: "r"(dst), "l"(src) : "memory");
}
#define CP_COMMIT() asm volatile("cp.async.commit_group;" ::: "memory")
#define CP_WAIT0()  asm volatile("cp.async.wait_group 0;" ::: "memory")

// A tile [m 128][k 32 halves] = 4 chunks/row.  2-row/128B atoms,
// slot = ((m&1)*4 + c) ^ ((m>>1)&7).  STS/cp.async phases and LDSM
// 8-row reads conflict-free (hand-checked; same scheme as R10/R11).
// Chunk pair (0,1)->(2,3) is byte-addr ^32.
__device__ __forceinline__ int a_off(int m, int c) {
    return ((m >> 1) * 32) + 4 * ((((m & 1) << 2) + c) ^ ((m >> 1) & 7));
}
// B tile [k 32][n 128 halves] = 16 chunks/row, perm = c ^ (r&7).
// ldsm.trans 8-row reads conflict-free; chunk+2 = ^32; k+16 = +4096B.
__device__ __forceinline__ int b_off(int r, int c) {
    return r * 64 + ((c ^ (r & 7)) << 2);
}
// Attention K/V tile [kv 64][d 64 halves] = 8 chunks/row, perm = c ^ (r&7).
__device__ __forceinline__ int k_off(int r, int c) {
    return r * 32 + ((c ^ (r & 7)) << 2);
}

// ---------------------------------------------------------------------------
__global__ void f2h_kernel(const float* __restrict__ s, __half* __restrict__ d, int n4)
{
    int i = blockIdx.x * blockDim.x + threadIdx.x;
    if (i < n4) {
        float4 v = ((const float4*)s)[i];
        uint2 h = { f2h2(v.x, v.y), f2h2(v.z, v.w) };
        ((uint2*)d)[i] = h;
    }
}

// ---------------------------------------------------------------------------
// C[M,N] = A[M,K] @ B[K,N] + bias.  fp16 in, fp32 accum, OUT_HALF selects
// fp16 or fp32 C.  Block 128x128, K-tile 32, 8 warps (2x4), warp 64x32.
// cp.async double-buffered; A via ldmatrix, B via ldmatrix.trans on [k][n].
// ---------------------------------------------------------------------------
template<bool OUT_HALF>
__global__ __launch_bounds__(256, 2)
void gemm_h(const __half* __restrict__ A, const __half* __restrict__ B,
            const float* __restrict__ bias, void* __restrict__ Cv,
            int M, int N, int K)
{
    __shared__ __align__(16) uint32_t As[2][2048];   // 8KB/buf
    __shared__ __align__(16) uint32_t Bs[2][2048];   // 8KB/buf

    const int tid  = threadIdx.x;
    const int w    = tid >> 5;
    const int lane = tid & 31;
    const int g    = lane >> 2;
    const int tig  = lane & 3;
    const int wm   = w >> 2;
    const int wn   = w & 3;
    const int bm   = blockIdx.y * 128;
    const int bn   = blockIdx.x * 128;

    // A cp.async: thread -> row tid>>1, chunks (tid&1)*2, +1
    const int ar  = tid >> 1;
    const int acb = (tid & 1) * 2;
    const __half* Ag = A + (size_t)(bm + ar) * K + acb * 8;
    const uint32_t aD0 = smem_u32(&As[0][a_off(ar, acb)]);
    const uint32_t aD1 = smem_u32(&As[0][a_off(ar, acb + 1)]);

    // B cp.async: ids tid, tid+256 -> rows tid>>4, +16; chunk tid&15
    const int brr = tid >> 4;
    const int bcc = tid & 15;
    const __half* Bg0 = B + (size_t)brr * N + bn + bcc * 8;
    const __half* Bg1 = Bg0 + (size_t)16 * N;
    const uint32_t bD0 = smem_u32(&Bs[0][b_off(brr, bcc)]);
    const uint32_t bD1 = smem_u32(&Bs[0][b_off(brr + 16, bcc)]);

    // ldmatrix addresses (loop-invariant)
    const int alr = lane & 15, alc = lane >> 4;
    uint32_t aL[4];
    #pragma unroll
    for (int mt = 0; mt < 4; mt++)
        aL[mt] = smem_u32(&As[0][a_off(wm * 64 + mt * 16 + alr, alc)]);
    const uint32_t bL = smem_u32(&Bs[0][b_off(lane & 15, wn * 4 + (lane >> 4))]);

    // prologue: k0 = 0 -> buffer 0
    cp16(aD0, Ag);  cp16(aD1, Ag + 8);
    cp16(bD0, Bg0); cp16(bD1, Bg1);
    CP_COMMIT();

    float acc[4][4][4];
    #pragma unroll
    for (int mt = 0; mt < 4; mt++)
        #pragma unroll
        for (int nt = 0; nt < 4; nt++)
            #pragma unroll
            for (int i = 0; i < 4; i++) acc[mt][nt][i] = 0.f;

    int buf = 0;
    for (int k0 = 0; k0 < K; k0 += 32) {
        CP_WAIT0();
        __syncthreads();
        if (k0 + 32 < K) {
            const int kn = k0 + 32;
            const uint32_t off = (uint32_t)(buf ^ 1) * 8192u;
            cp16(aD0 + off, Ag + kn);
            cp16(aD1 + off, Ag + kn + 8);
            cp16(bD0 + off, Bg0 + (size_t)kn * N);
            cp16(bD1 + off, Bg1 + (size_t)kn * N);
            CP_COMMIT();
        }
        const uint32_t bo = (uint32_t)buf * 8192u;
        #pragma unroll
        for (int ks = 0; ks < 2; ks++) {
            const uint32_t kx = (uint32_t)ks << 5;
            uint32_t af[4][4], bq0[4], bq1[4];
            #pragma unroll
            for (int mt = 0; mt < 4; mt++)
                ldsm_x4(af[mt], (aL[mt] + bo) ^ kx);
            const uint32_t bAdr = bL + bo + ks * 4096u;
            ldsm_x4_t(bq0, bAdr);
            ldsm_x4_t(bq1, bAdr ^ 32u);
            #pragma unroll
            for (int mt = 0; mt < 4; mt++) {
                mma_f16(acc[mt][0], af[mt], bq0[0], bq0[1]);
                mma_f16(acc[mt][1], af[mt], bq0[2], bq0[3]);
                mma_f16(acc[mt][2], af[mt], bq1[0], bq1[1]);
                mma_f16(acc[mt][3], af[mt], bq1[2], bq1[3]);
            }
        }
        buf ^= 1;
    }

    // epilogue
    #pragma unroll
    for (int mt = 0; mt < 4; mt++) {
        const int row = bm + wm * 64 + mt * 16 + g;
        #pragma unroll
        for (int nt = 0; nt < 4; nt++) {
            const int col = bn + wn * 32 + nt * 8 + 2 * tig;
            const float bv0 = __ldg(bias + col), bv1 = __ldg(bias + col + 1);
            if (OUT_HALF) {
                __half* C = (__half*)Cv;
                *(uint32_t*)(C + (size_t)row * N + col)       = f2h2(acc[mt][nt][0] + bv0, acc[mt][nt][1] + bv1);
                *(uint32_t*)(C + (size_t)(row + 8) * N + col) = f2h2(acc[mt][nt][2] + bv0, acc[mt][nt][3] + bv1);
            } else {
                float* C = (float*)Cv;
                float2 v0 = { acc[mt][nt][0] + bv0, acc[mt][nt][1] + bv1 };
                float2 v1 = { acc[mt][nt][2] + bv0, acc[mt][nt][3] + bv1 };
                *(float2*)(C + (size_t)row * N + col) = v0;
                *(float2*)(C + (size_t)(row + 8) * N + col) = v1;
            }
        }
    }
}

// ---------------------------------------------------------------------------
// Causal flash attention, fp16 qkv in, fp16 out.  One block per
// (qtile=64, head, batch), 4 warps.  cp.async double-buffered K/V tiles;
// K via ldmatrix, V via ldmatrix.trans; P stays in registers.
// ---------------------------------------------------------------------------
__global__ __launch_bounds__(128)
void attn_h(const __half* __restrict__ qkv, __half* __restrict__ outp)
{
    __shared__ __align__(16) uint32_t Ks[2][2048];   // 8KB/buf
    __shared__ __align__(16) uint32_t Vs[2][2048];

    const int tid  = threadIdx.x;
    const int w    = tid >> 5;
    const int lane = tid & 31;
    const int g    = lane >> 2;
    const int tig  = lane & 3;
    const int qt   = blockIdx.x;
    const int h    = blockIdx.y;
    const int b    = blockIdx.z;

    const size_t rs = 3 * NE;
    const __half* base = qkv + (size_t)b * NS * rs;
    const __half* qptr = base + h * NHD;
    const __half* kptr = base + NE + h * NHD;
    const __half* vptr = base + 2 * NE + h * NHD;

    const int qrow0 = qt * 64 + w * 16;

    // Q fragments (x 0.125 exact in fp16)
    const __half2 s8 = __floats2half2_rn(0.125f, 0.125f);
    uint32_t qf[4][4];
    #pragma unroll
    for (int kt = 0; kt < 4; kt++) {
        const int d0 = kt * 16 + 2 * tig;
        const __half* r0 = qptr + (size_t)(qrow0 + g) * rs;
        const __half* r1 = qptr + (size_t)(qrow0 + g + 8) * rs;
        __half2 h0 = __hmul2(*(const __half2*)(r0 + d0), s8);
        __half2 h1 = __hmul2(*(const __half2*)(r1 + d0), s8);
        __half2 h2 = __hmul2(*(const __half2*)(r0 + d0 + 8), s8);
        __half2 h3 = __hmul2(*(const __half2*)(r1 + d0 + 8), s8);
        qf[kt][0] = *(uint32_t*)&h0; qf[kt][1] = *(uint32_t*)&h1;
        qf[kt][2] = *(uint32_t*)&h2; qf[kt][3] = *(uint32_t*)&h3;
    }

    // cp.async mapping: chunk c = tid&7 fixed; rows r_i = tid>>3 + 16*i
    const int cc = tid & 7;
    const int r0i = tid >> 3;
    uint32_t kD[4], vD[4];
    size_t srcOff[4];
    #pragma unroll
    for (int i = 0; i < 4; i++) {
        const int r = r0i + 16 * i;
        kD[i] = smem_u32(&Ks[0][k_off(r, cc)]);
        vD[i] = smem_u32(&Vs[0][k_off(r, cc)]);
        srcOff[i] = (size_t)r * rs + cc * 8;
    }

    // ldmatrix bases
    const int klr = ((lane >> 4) << 3) + (lane & 7);
    const int klc = (lane >> 3) & 1;
    const uint32_t kBase = smem_u32(&Ks[0][k_off(klr, klc)]);
    const int vlr = lane & 15;
    const int vlc = lane >> 4;
    const uint32_t vBase = smem_u32(&Vs[0][k_off(vlr, vlc)]);

    float o[8][4];
    #pragma unroll
    for (int nt = 0; nt < 8; nt++)
        #pragma unroll
        for (int i = 0; i < 4; i++) o[nt][i] = 0.f;
    float m0 = -INFINITY, m1 = -INFINITY;
    float l0 = 0.f, l1 = 0.f;

    // prologue: j = 0 -> buffer 0
    #pragma unroll
    for (int i = 0; i < 4; i++) {
        cp16(kD[i], kptr + srcOff[i]);
        cp16(vD[i], vptr + srcOff[i]);
    }
    CP_COMMIT();

    int buf = 0;
    for (int j = 0; j <= qt; j++) {
        CP_WAIT0();
        __syncthreads();
        if (j < qt) {
            const uint32_t off = (uint32_t)(buf ^ 1) * 8192u;
            const size_t jo = (size_t)(j + 1) * 64 * rs;
            #pragma unroll
            for (int i = 0; i < 4; i++) {
                cp16(kD[i] + off, kptr + jo + srcOff[i]);
                cp16(vD[i] + off, vptr + jo + srcOff[i]);
            }
            CP_COMMIT();
        }
        const uint32_t bo = (uint32_t)buf * 8192u;

        // S = Q @ K^T  (16 x 64 per warp)
        float sc[8][4];
        #pragma unroll
        for (int nt = 0; nt < 8; nt++)
            #pragma unroll
            for (int i = 0; i < 4; i++) sc[nt][i] = 0.f;
        #pragma unroll
        for (int kt = 0; kt < 4; kt++) {
            #pragma unroll
            for (int p = 0; p < 4; p++) {
                uint32_t bq[4];
                ldsm_x4(bq, (kBase + bo + p * 2048u) ^ ((uint32_t)kt << 5));
                mma_f16(sc[2 * p],     qf[kt], bq[0], bq[1]);
                mma_f16(sc[2 * p + 1], qf[kt], bq[2], bq[3]);
            }
        }

        if (j == qt) {
            const int r0g = qrow0 + g, r1g = qrow0 + g + 8;
            #pragma unroll
            for (int nt = 0; nt < 8; nt++) {
                const int col = j * 64 + nt * 8 + 2 * tig;
                if (col     > r0g) sc[nt][0] = -1e30f;
                if (col + 1 > r0g) sc[nt][1] = -1e30f;
                if (col     > r1g) sc[nt][2] = -1e30f;
                if (col + 1 > r1g) sc[nt][3] = -1e30f;
            }
        }

        float mt0 = -1e30f, mt1 = -1e30f;
        #pragma unroll
        for (int nt = 0; nt < 8; nt++) {
            mt0 = fmaxf(mt0, fmaxf(sc[nt][0], sc[nt][1]));
            mt1 = fmaxf(mt1, fmaxf(sc[nt][2], sc[nt][3]));
        }
        mt0 = fmaxf(mt0, __shfl_xor_sync(0xffffffffu, mt0, 1));
        mt0 = fmaxf(mt0, __shfl_xor_sync(0xffffffffu, mt0, 2));
        mt1 = fmaxf(mt1, __shfl_xor_sync(0xffffffffu, mt1, 1));
        mt1 = fmaxf(mt1, __shfl_xor_sync(0xffffffffu, mt1, 2));

        const float mn0 = fmaxf(m0, mt0), mn1 = fmaxf(m1, mt1);
        const float al0 = __expf(m0 - mn0), al1 = __expf(m1 - mn1);
        m0 = mn0; m1 = mn1;

        uint32_t ph[8][2];
        float rs0 = 0.f, rs1 = 0.f;
        #pragma unroll
        for (int nt = 0; nt < 8; nt++) {
            const float p0 = __expf(sc[nt][0] - mn0);
            const float p1 = __expf(sc[nt][1] - mn0);
            const float p2 = __expf(sc[nt][2] - mn1);
            const float p3 = __expf(sc[nt][3] - mn1);
            rs0 += p0 + p1;
            rs1 += p2 + p3;
            ph[nt][0] = f2h2(p0, p1);
            ph[nt][1] = f2h2(p2, p3);
            o[nt][0] *= al0; o[nt][1] *= al0;
            o[nt][2] *= al1; o[nt][3] *= al1;
        }
        rs0 += __shfl_xor_sync(0xffffffffu, rs0, 1);
        rs0 += __shfl_xor_sync(0xffffffffu, rs0, 2);
        rs1 += __shfl_xor_sync(0xffffffffu, rs1, 1);
        rs1 += __shfl_xor_sync(0xffffffffu, rs1, 2);
        l0 = l0 * al0 + rs0;
        l1 = l1 * al1 + rs1;

        // O += P @ V
        #pragma unroll
        for (int kt = 0; kt < 4; kt++) {
            uint32_t pa[4] = { ph[2 * kt][0], ph[2 * kt][1],
                               ph[2 * kt + 1][0], ph[2 * kt + 1][1] };
            #pragma unroll
            for (int p = 0; p < 4; p++) {
                uint32_t vq[4];
                ldsm_x4_t(vq, (vBase + bo + kt * 2048u) ^ ((uint32_t)p << 5));
                mma_f16(o[2 * p],     pa, vq[0], vq[1]);
                mma_f16(o[2 * p + 1], pa, vq[2], vq[3]);
            }
        }
        buf ^= 1;
    }

    const float inv0 = 1.f / l0, inv1 = 1.f / l1;
    const size_t orow0 = (size_t)b * NS + qrow0 + g;
    #pragma unroll
    for (int nt = 0; nt < 8; nt++) {
        const int col = h * NHD + nt * 8 + 2 * tig;
        *(uint32_t*)(outp + orow0 * NE + col)       = f2h2(o[nt][0] * inv0, o[nt][1] * inv0);
        *(uint32_t*)(outp + (orow0 + 8) * NE + col) = f2h2(o[nt][2] * inv1, o[nt][3] * inv1);
    }
}

// ---------------------------------------------------------------------------
extern "C" void kernel_launch(void* const* d_in, const int* in_sizes, int n_in,
                              void* d_out, int out_size)
{
    (void)in_sizes; (void)n_in; (void)out_size;
    const float* Q  = (const float*)d_in[0];
    const float* Wp = (const float*)d_in[1];
    const float* bp = (const float*)d_in[2];
    const float* Wo = (const float*)d_in[3];
    const float* bo = (const float*)d_in[4];
    float* out = (float*)d_out;

    void *qh, *wph, *woh, *qkvh, *attnh;
    cudaGetSymbolAddress(&qh, g_Qh);
    cudaGetSymbolAddress(&wph, g_Wph);
    cudaGetSymbolAddress(&woh, g_Woh);
    cudaGetSymbolAddress(&qkvh, g_qkvh);
    cudaGetSymbolAddress(&attnh, g_attnh);

    const int M = NB * NS;  // 8192

    const int nQ  = M * NE / 4;
    const int nWp = NE * 3 * NE / 4;
    const int nWo = NE * NE / 4;
    f2h_kernel<<<(nQ  + 255) / 256, 256>>>(Q,  (__half*)qh,  nQ);
    f2h_kernel<<<(nWp + 255) / 256, 256>>>(Wp, (__half*)wph, nWp);
    f2h_kernel<<<(nWo + 255) / 256, 256>>>(Wo, (__half*)woh, nWo);

    gemm_h<true><<<dim3((3 * NE) / 128, M / 128), 256>>>(
        (const __half*)qh, (const __half*)wph, bp, qkvh, M, 3 * NE, NE);
    attn_h<<<dim3(NS / 64, NH, NB), 128>>>((const __half*)qkvh, (__half*)attnh);
    gemm_h<false><<<dim3(NE / 128, M / 128), 256>>>(
        (const __half*)attnh, (const __half*)woh, bo, out, M, NE, NE);
}